// round 10
// baseline (speedup 1.0000x reference)
#include <cuda_runtime.h>
#include <cuda_fp16.h>
#include <cstdint>

// ============================================================================
// Problem constants
// ============================================================================
#define EDIM 256      // E
#define HIDN 512      // 2E
#define KIN  768      // 3E
#define BTOT 131072

// ============================================================================
// Device scratch (allocation-free rule: __device__ globals)
// ============================================================================
__device__ float  g_M[6 * EDIM * EDIM];                  // M_i = Wo_i @ Wv_i (atomic-accum)
__device__ float  g_B1f[HIDN * KIN];                     // fold term, fp32 (atomic-accum)
__device__ float  g_cvec[6 * EDIM];                      // c_i = Wo_i @ bv_i + bo_i
__device__ float  g_b1eff[HIDN];                         // b1 + Kvec @ W1^T
__device__ __align__(16) __half g_B1h[HIDN * KIN];       // folded W1, fp16 [N=512][K=768]
__device__ __align__(16) __half g_W2h[EDIM * HIDN];      // W2 fp16 [N=256][K=512]
__device__ __align__(16) __half g_H[(size_t)BTOT * HIDN];// hidden fp16 [131072][512]

// ============================================================================
// PTX helpers (baseline sm_80+ features only: mma.sync / ldmatrix / cp.async)
// ============================================================================
__device__ __forceinline__ uint32_t smem_u32(const void* p) {
    uint32_t a;
    asm("{ .reg .u64 t; cvta.to.shared.u64 t, %1; cvt.u32.u64 %0, t; }" : "=r"(a) : "l"(p));
    return a;
}

__device__ __forceinline__ void cp_async16(uint32_t saddr, const void* gaddr) {
    asm volatile("cp.async.cg.shared.global [%0], [%1], 16;" :: "r"(saddr), "l"(gaddr));
}
__device__ __forceinline__ void cp_commit() { asm volatile("cp.async.commit_group;" ::: "memory"); }
__device__ __forceinline__ void cp_wait0()  { asm volatile("cp.async.wait_group 0;" ::: "memory"); }

__device__ __forceinline__ void ldm_x4(uint32_t& r0, uint32_t& r1, uint32_t& r2, uint32_t& r3,
                                       uint32_t addr) {
    asm volatile("ldmatrix.sync.aligned.m8n8.x4.shared.b16 {%0,%1,%2,%3}, [%4];"
                 : "=r"(r0), "=r"(r1), "=r"(r2), "=r"(r3) : "r"(addr));
}

__device__ __forceinline__ void mma16816(float* c, uint32_t a0, uint32_t a1, uint32_t a2,
                                         uint32_t a3, uint32_t b0, uint32_t b1) {
    asm volatile(
        "mma.sync.aligned.m16n8k16.row.col.f32.f16.f16.f32 "
        "{%0,%1,%2,%3}, {%4,%5,%6,%7}, {%8,%9}, {%0,%1,%2,%3};"
        : "+f"(c[0]), "+f"(c[1]), "+f"(c[2]), "+f"(c[3])
        : "r"(a0), "r"(a1), "r"(a2), "r"(a3), "r"(b0), "r"(b1));
}

// XOR swizzle for a [128 rows][64 halves] tile (128B rows, 16B units, 8-way)
__device__ __forceinline__ uint32_t swz(uint32_t row, uint32_t k) {
    return row * 128u + ((((k >> 3) ^ (row & 7)) << 4) | ((k & 7) * 2u));
}

// ============================================================================
// Precompute kernels — deeper split-K (R9 ncu: k_B1 23.5us @ occ 29%, still
// parallelism-starved)
// ============================================================================

// zero the atomic-accumulated scratch (g_M, g_B1f), 786432 floats total
__global__ void k_zero() {
    size_t i = (size_t)blockIdx.x * 256 + threadIdx.x;   // grid 384
    float4 z = {0.f, 0.f, 0.f, 0.f};
    ((float4*)g_M)[i]   = z;
    ((float4*)g_B1f)[i] = z;
}

// M_i = Wo_i @ Wv_i, split-K x4: grid (4, 4, 24); z = i*4 + quarter (K chunk 64)
__global__ void __launch_bounds__(256) k_M(const float* __restrict__ Wo,
                                           const float* __restrict__ Wv) {
    const int z  = blockIdx.z;
    const int i  = z >> 2;
    const int mbase = (z & 3) * 64;
    const int k0 = blockIdx.x * 64, e0 = blockIdx.y * 64;
    const int tid = threadIdx.x;
    __shared__ float sA[64][17];
    __shared__ float sB[16][65];
    const float* A  = Wo + i * 65536;
    const float* Bm = Wv + i * 65536;
    float acc[4][4] = {};
    const int ty = tid >> 4, tx = tid & 15;
    for (int m0 = mbase; m0 < mbase + 64; m0 += 16) {
        {
            int e = tid >> 4, mm = tid & 15;
#pragma unroll
            for (int r = 0; r < 4; r++)
                sA[r * 16 + e][mm] = A[(e0 + r * 16 + e) * 256 + m0 + mm];
        }
        {
            int mm = tid >> 6, kk = tid & 63;
#pragma unroll
            for (int r = 0; r < 4; r++)
                sB[r * 4 + mm][kk] = Bm[(m0 + r * 4 + mm) * 256 + k0 + kk];
        }
        __syncthreads();
#pragma unroll
        for (int kk = 0; kk < 16; kk++) {
            float a[4], b[4];
#pragma unroll
            for (int x = 0; x < 4; x++) a[x] = sA[ty * 4 + x][kk];
#pragma unroll
            for (int x = 0; x < 4; x++) b[x] = sB[kk][tx * 4 + x];
#pragma unroll
            for (int x = 0; x < 4; x++)
#pragma unroll
                for (int y = 0; y < 4; y++) acc[x][y] += a[x] * b[y];
        }
        __syncthreads();
    }
#pragma unroll
    for (int x = 0; x < 4; x++)
#pragma unroll
        for (int y = 0; y < 4; y++)
            atomicAdd(&g_M[i * 65536 + (e0 + ty * 4 + x) * 256 + k0 + tx * 4 + y], acc[x][y]);
}

// c_i = Wo_i @ bv_i + bo_i
__global__ void k_cvec(const float* __restrict__ Wo, const float* __restrict__ bv,
                       const float* __restrict__ bo) {
    int i = blockIdx.x, e = threadIdx.x;
    const float* w = Wo + i * 65536 + e * 256;
    const float* b = bv + i * 256;
    float a0 = 0.f, a1 = 0.f, a2 = 0.f, a3 = 0.f;
#pragma unroll 4
    for (int m = 0; m < 256; m += 4) {
        a0 += w[m + 0] * b[m + 0];
        a1 += w[m + 1] * b[m + 1];
        a2 += w[m + 2] * b[m + 2];
        a3 += w[m + 3] * b[m + 3];
    }
    g_cvec[i * 256 + e] = bo[i * 256 + e] + (a0 + a1) + (a2 + a3);
}

// fold term: g_B1f[n][k] += sum_e W1[n][q*256+e] * M[idx(r,q)][e][k%256]
// split x8: grid (12, 8, 8); z>>2 selects q (of the two != r), z&3 selects e-quarter
__global__ void __launch_bounds__(256) k_B1(const float* __restrict__ W1) {
    const int k0 = blockIdx.x * 64, n0 = blockIdx.y * 64;
    const int r = k0 >> 8;
    const int kp0 = k0 & 255;
    const int z = blockIdx.z;
    const int qi = z >> 2;
    const int q = (qi == 0) ? (r == 0 ? 1 : 0) : (r == 2 ? 1 : 2);
    // module index: kv-input r, query q:
    // (r,q): (0,1)->2 (0,2)->4 (1,0)->0 (1,2)->5 (2,0)->1 (2,1)->3
    const int midx = (r == 0) ? (q == 1 ? 2 : 4)
                   : (r == 1) ? (q == 0 ? 0 : 5)
                              : (q == 0 ? 1 : 3);
    const int ebase = (z & 3) * 64;
    const int tid = threadIdx.x;
    __shared__ float sA[64][17];
    __shared__ float sB[16][65];
    float acc[4][4] = {};
    const int ty = tid >> 4, tx = tid & 15;
    const float* Mb = g_M + midx * 65536;
    for (int e0 = ebase; e0 < ebase + 64; e0 += 16) {
        {
            int n = tid >> 4, ee = tid & 15;
#pragma unroll
            for (int rr = 0; rr < 4; rr++)
                sA[rr * 16 + n][ee] = W1[(n0 + rr * 16 + n) * KIN + q * 256 + e0 + ee];
        }
        {
            int ee = tid >> 6, kk = tid & 63;
#pragma unroll
            for (int rr = 0; rr < 4; rr++)
                sB[rr * 4 + ee][kk] = Mb[(e0 + rr * 4 + ee) * 256 + kp0 + kk];
        }
        __syncthreads();
#pragma unroll
        for (int kk = 0; kk < 16; kk++) {
            float a[4], b[4];
#pragma unroll
            for (int x = 0; x < 4; x++) a[x] = sA[ty * 4 + x][kk];
#pragma unroll
            for (int x = 0; x < 4; x++) b[x] = sB[kk][tx * 4 + x];
#pragma unroll
            for (int x = 0; x < 4; x++)
#pragma unroll
                for (int y = 0; y < 4; y++) acc[x][y] += a[x] * b[y];
        }
        __syncthreads();
    }
#pragma unroll
    for (int x = 0; x < 4; x++)
#pragma unroll
        for (int y = 0; y < 4; y++) {
            int n = n0 + ty * 4 + x, k = k0 + tx * 4 + y;
            atomicAdd(&g_B1f[n * KIN + k], acc[x][y]);
        }
}

// finalize: B1h = fp16(W1 + fold) [blocks 0..1535] ; W2h = fp16(W2) [1536..2047]
__global__ void k_fin(const float* __restrict__ W1, const float* __restrict__ W2) {
    int bi = blockIdx.x;
    if (bi < 1536) {
        int idx = bi * 256 + threadIdx.x;
        g_B1h[idx] = __float2half_rn(W1[idx] + g_B1f[idx]);
    } else {
        int idx = (bi - 1536) * 256 + threadIdx.x;
        g_W2h[idx] = __float2half_rn(W2[idx]);
    }
}

// b1eff[n] = b1[n] + sum_j csum[j] * W1[n][j]
__global__ void __launch_bounds__(256) k_b1eff(const float* __restrict__ W1,
                                               const float* __restrict__ b1) {
    const int n = blockIdx.x;
    const int tid = threadIdx.x;
    float p = 0.f;
#pragma unroll
    for (int jj = 0; jj < 3; jj++) {
        int j = jj * 256 + tid;
        int q = j >> 8, e = j & 255;
        float cs = g_cvec[(2 * q) * 256 + e] + g_cvec[(2 * q + 1) * 256 + e];
        p += cs * W1[n * KIN + j];
    }
    __shared__ float red[256];
    red[tid] = p;
    __syncthreads();
#pragma unroll
    for (int s = 128; s > 0; s >>= 1) {
        if (tid < s) red[tid] += red[tid + s];
        __syncthreads();
    }
    if (tid == 0) g_b1eff[n] = b1[n] + red[0];
}

// ============================================================================
// GEMM1 (R6 winner): hidden[B,512] = relu(X[B,768] @ B1h^T + b1eff)
// 256 thr, tile 128x128, warp tile 64x32, K-chunk 64, double-buffered, occ 2
// ============================================================================
#define SM_A0 0
#define SM_A1 16384
#define SM_B0 32768
#define SM_B1 49152
#define SMEM_G 65536

__global__ void __launch_bounds__(256, 2)
gemm1(const float* __restrict__ gE, const float* __restrict__ dE,
      const float* __restrict__ cE) {
    extern __shared__ char smem[];
    const uint32_t sb = smem_u32(smem);
    const int tid = threadIdx.x;
    const int wid = tid >> 5, lane = tid & 31;
    const int m0 = blockIdx.y * 128;
    const int n0 = blockIdx.x * 128;
    const int wm = (wid >> 2) * 64;
    const int wn = (wid & 3) * 32;
    const float* srcs[3] = {gE, dE, cE};

    float acc[4][4][4];
#pragma unroll
    for (int i = 0; i < 4; i++)
#pragma unroll
        for (int j = 0; j < 4; j++)
#pragma unroll
            for (int v = 0; v < 4; v++) acc[i][j][v] = 0.f;

    const int a_row[8] = { (0*256+tid) >> 4, (1*256+tid) >> 4, (2*256+tid) >> 4, (3*256+tid) >> 4,
                           (4*256+tid) >> 4, (5*256+tid) >> 4, (6*256+tid) >> 4, (7*256+tid) >> 4 };
    const int a_c4 = tid & 15;

    uint2 ah[8];   // A fragment converted to fp16 at load time

    // prologue: buffer 0 (kc = 0)
    {
        const float* src = srcs[0] + (size_t)m0 * 256;
#pragma unroll
        for (int i = 0; i < 8; i++) {
            float4 f = *(const float4*)(src + (size_t)a_row[i] * 256 + a_c4 * 4);
            __half2 h0 = __floats2half2_rn(f.x, f.y);
            __half2 h1 = __floats2half2_rn(f.z, f.w);
            ah[i].x = *(uint32_t*)&h0;
            ah[i].y = *(uint32_t*)&h1;
        }
#pragma unroll
        for (int i = 0; i < 8; i++)
            *(uint2*)(smem + SM_A0 + swz(a_row[i], a_c4 * 4)) = ah[i];
#pragma unroll
        for (int i = 0; i < 4; i++) {
            int idx = i * 256 + tid;
            int row = idx >> 3, c = idx & 7;
            cp_async16(sb + SM_B0 + swz(row, c * 8), g_B1h + (size_t)(n0 + row) * KIN + c * 8);
        }
        cp_commit();
        cp_wait0();
        __syncthreads();
    }

    const int NITER = 12;
    for (int kc = 0; kc < NITER; kc++) {
        const uint32_t Abase = sb + (kc & 1 ? SM_A1 : SM_A0);
        const uint32_t Bbase = sb + (kc & 1 ? SM_B1 : SM_B0);
        const int nxt = kc + 1;
        const uint32_t AbaseN = sb + (nxt & 1 ? SM_A1 : SM_A0);
        const uint32_t BbaseN = sb + (nxt & 1 ? SM_B1 : SM_B0);

        if (nxt < NITER) {
            const float* src = srcs[nxt >> 2] + (size_t)m0 * 256 + (nxt & 3) * 64;
#pragma unroll
            for (int i = 0; i < 8; i++) {
                float4 f = *(const float4*)(src + (size_t)a_row[i] * 256 + a_c4 * 4);
                __half2 h0 = __floats2half2_rn(f.x, f.y);
                __half2 h1 = __floats2half2_rn(f.z, f.w);
                ah[i].x = *(uint32_t*)&h0;
                ah[i].y = *(uint32_t*)&h1;
            }
#pragma unroll
            for (int i = 0; i < 4; i++) {
                int idx = i * 256 + tid;
                int row = idx >> 3, c = idx & 7;
                cp_async16(BbaseN + swz(row, c * 8),
                           g_B1h + (size_t)(n0 + row) * KIN + nxt * 64 + c * 8);
            }
            cp_commit();
        }

        // compute on current buffers
#pragma unroll
        for (int ks = 0; ks < 64; ks += 16) {
            uint32_t a[4][4], b[8];
#pragma unroll
            for (int t = 0; t < 4; t++) {
                uint32_t row = wm + t * 16 + (lane & 15);
                uint32_t kk  = ks + (lane >> 4) * 8;
                ldm_x4(a[t][0], a[t][1], a[t][2], a[t][3], Abase + swz(row, kk));
            }
#pragma unroll
            for (int h = 0; h < 2; h++) {
                int g = lane >> 3, ri = lane & 7;
                uint32_t nrow = wn + h * 16 + (g >> 1) * 8 + ri;
                uint32_t kk   = ks + (g & 1) * 8;
                ldm_x4(b[h * 4 + 0], b[h * 4 + 1], b[h * 4 + 2], b[h * 4 + 3],
                       Bbase + swz(nrow, kk));
            }
#pragma unroll
            for (int mt = 0; mt < 4; mt++)
#pragma unroll
                for (int nt = 0; nt < 4; nt++)
                    mma16816(acc[mt][nt], a[mt][0], a[mt][1], a[mt][2], a[mt][3],
                             b[nt * 2], b[nt * 2 + 1]);
        }

        if (nxt < NITER) {
#pragma unroll
            for (int i = 0; i < 8; i++)
                *(uint2*)((char*)smem + (AbaseN - sb) + swz(a_row[i], a_c4 * 4)) = ah[i];
            cp_wait0();
        }
        __syncthreads();
    }

    // epilogue: relu(acc + b1eff) -> fp16 g_H
#pragma unroll
    for (int mt = 0; mt < 4; mt++) {
#pragma unroll
        for (int nt = 0; nt < 4; nt++) {
            int n = n0 + wn + nt * 8 + (lane & 3) * 2;
            float bia0 = g_b1eff[n], bia1 = g_b1eff[n + 1];
            int r0 = m0 + wm + mt * 16 + (lane >> 2);
            float v0 = fmaxf(acc[mt][nt][0] + bia0, 0.f);
            float v1 = fmaxf(acc[mt][nt][1] + bia1, 0.f);
            float v2 = fmaxf(acc[mt][nt][2] + bia0, 0.f);
            float v3 = fmaxf(acc[mt][nt][3] + bia1, 0.f);
            __half2 h01 = __floats2half2_rn(v0, v1);
            __half2 h23 = __floats2half2_rn(v2, v3);
            *(__half2*)(g_H + (size_t)r0 * HIDN + n)       = h01;
            *(__half2*)(g_H + (size_t)(r0 + 8) * HIDN + n) = h23;
        }
    }
}

// ============================================================================
// GEMM2 (R6 winner): out[B,256] = g_H[B,512] @ W2h^T + b2, fp32 out, occ 2
// ============================================================================
__global__ void __launch_bounds__(256, 2)
gemm2(const float* __restrict__ b2, float* __restrict__ out) {
    extern __shared__ char smem[];
    const uint32_t sb = smem_u32(smem);
    const int tid = threadIdx.x;
    const int wid = tid >> 5, lane = tid & 31;
    const int m0 = blockIdx.y * 128;
    const int n0 = blockIdx.x * 128;
    const int wm = (wid >> 2) * 64;
    const int wn = (wid & 3) * 32;

    float acc[4][4][4];
#pragma unroll
    for (int i = 0; i < 4; i++)
#pragma unroll
        for (int j = 0; j < 4; j++)
#pragma unroll
            for (int v = 0; v < 4; v++) acc[i][j][v] = 0.f;

    // prologue buffer 0
    {
#pragma unroll
        for (int i = 0; i < 4; i++) {
            int idx = i * 256 + tid;
            int row = idx >> 3, c = idx & 7;
            cp_async16(sb + SM_A0 + swz(row, c * 8), g_H + (size_t)(m0 + row) * HIDN + c * 8);
            cp_async16(sb + SM_B0 + swz(row, c * 8), g_W2h + (size_t)(n0 + row) * HIDN + c * 8);
        }
        cp_commit();
        cp_wait0();
        __syncthreads();
    }

    const int NITER = 8;
    for (int kc = 0; kc < NITER; kc++) {
        const uint32_t Abase = sb + (kc & 1 ? SM_A1 : SM_A0);
        const uint32_t Bbase = sb + (kc & 1 ? SM_B1 : SM_B0);
        const int nxt = kc + 1;

        if (nxt < NITER) {
            uint32_t AbaseN = sb + (nxt & 1 ? SM_A1 : SM_A0);
            uint32_t BbaseN = sb + (nxt & 1 ? SM_B1 : SM_B0);
#pragma unroll
            for (int i = 0; i < 4; i++) {
                int idx = i * 256 + tid;
                int row = idx >> 3, c = idx & 7;
                cp_async16(AbaseN + swz(row, c * 8),
                           g_H + (size_t)(m0 + row) * HIDN + nxt * 64 + c * 8);
                cp_async16(BbaseN + swz(row, c * 8),
                           g_W2h + (size_t)(n0 + row) * HIDN + nxt * 64 + c * 8);
            }
            cp_commit();
        }

#pragma unroll
        for (int ks = 0; ks < 64; ks += 16) {
            uint32_t a[4][4], b[8];
#pragma unroll
            for (int t = 0; t < 4; t++) {
                uint32_t row = wm + t * 16 + (lane & 15);
                uint32_t kk  = ks + (lane >> 4) * 8;
                ldm_x4(a[t][0], a[t][1], a[t][2], a[t][3], Abase + swz(row, kk));
            }
#pragma unroll
            for (int h = 0; h < 2; h++) {
                int g = lane >> 3, ri = lane & 7;
                uint32_t nrow = wn + h * 16 + (g >> 1) * 8 + ri;
                uint32_t kk   = ks + (g & 1) * 8;
                ldm_x4(b[h * 4 + 0], b[h * 4 + 1], b[h * 4 + 2], b[h * 4 + 3],
                       Bbase + swz(nrow, kk));
            }
#pragma unroll
            for (int mt = 0; mt < 4; mt++)
#pragma unroll
                for (int nt = 0; nt < 4; nt++)
                    mma16816(acc[mt][nt], a[mt][0], a[mt][1], a[mt][2], a[mt][3],
                             b[nt * 2], b[nt * 2 + 1]);
        }

        if (nxt < NITER) cp_wait0();
        __syncthreads();
    }

    // epilogue: acc + b2 -> fp32 out
#pragma unroll
    for (int mt = 0; mt < 4; mt++) {
#pragma unroll
        for (int nt = 0; nt < 4; nt++) {
            int n = n0 + wn + nt * 8 + (lane & 3) * 2;
            float bia0 = b2[n], bia1 = b2[n + 1];
            int r0 = m0 + wm + mt * 16 + (lane >> 2);
            float2 o01 = { acc[mt][nt][0] + bia0, acc[mt][nt][1] + bia1 };
            float2 o23 = { acc[mt][nt][2] + bia0, acc[mt][nt][3] + bia1 };
            *(float2*)(out + (size_t)r0 * EDIM + n)       = o01;
            *(float2*)(out + (size_t)(r0 + 8) * EDIM + n) = o23;
        }
    }
}

// ============================================================================
// kernel_launch
// Input order: g, d, c, Wq, Wk, Wv, bq, bk, bv, Wo, bo, W1, b1, W2, b2
// ============================================================================
extern "C" void kernel_launch(void* const* d_in, const int* in_sizes, int n_in,
                              void* d_out, int out_size) {
    const float* g  = (const float*)d_in[0];
    const float* dd = (const float*)d_in[1];
    const float* cc = (const float*)d_in[2];
    const float* Wv = (const float*)d_in[5];
    const float* bv = (const float*)d_in[8];
    const float* Wo = (const float*)d_in[9];
    const float* bo = (const float*)d_in[10];
    const float* W1 = (const float*)d_in[11];
    const float* b1 = (const float*)d_in[12];
    const float* W2 = (const float*)d_in[13];
    const float* b2 = (const float*)d_in[14];
    const int B = in_sizes[0] / EDIM;

    // Precompute: zero scratch, then deep split-K folds
    k_zero <<<384, 256>>>();                       // g_M, g_B1f = 0
    k_cvec <<<6, 256>>>(Wo, bv, bo);
    k_M    <<<dim3(4, 4, 24), 256>>>(Wo, Wv);      // split-K x4
    k_B1   <<<dim3(12, 8, 8), 256>>>(W1);          // split x8 (per-q, per-e-quarter)
    k_b1eff<<<HIDN, 256>>>(W1, b1);
    k_fin  <<<2048, 256>>>(W1, W2);                // B1h + W2h in one launch

    cudaFuncSetAttribute(gemm1, cudaFuncAttributeMaxDynamicSharedMemorySize, SMEM_G);
    cudaFuncSetAttribute(gemm2, cudaFuncAttributeMaxDynamicSharedMemorySize, SMEM_G);

    gemm1<<<dim3(4, B / 128), 256, SMEM_G>>>(g, dd, cc);
    gemm2<<<dim3(2, B / 128), 256, SMEM_G>>>(b2, (float*)d_out);
}

// round 11
// speedup vs baseline: 1.0176x; 1.0176x over previous
#include <cuda_runtime.h>
#include <cuda_fp16.h>
#include <cstdint>

// ============================================================================
// Problem constants
// ============================================================================
#define EDIM 256      // E
#define HIDN 512      // 2E
#define KIN  768      // 3E
#define BTOT 131072

// ============================================================================
// Device scratch (allocation-free rule: __device__ globals)
// ============================================================================
__device__ float  g_M[6 * EDIM * EDIM];                  // M_i = Wo_i @ Wv_i (atomic-accum)
__device__ float  g_cvec[6 * EDIM];                      // c_i = Wo_i @ bv_i + bo_i
__device__ float  g_b1eff[HIDN];                         // b1 + Kvec @ W1^T
__device__ __align__(16) __half g_W1h[HIDN * KIN];       // W1 fp16
__device__ __align__(16) __half g_Bc[3 * EDIM * HIDN];   // repacked M: [r][kp][qe] fp16
__device__ __align__(16) __half g_B1h[HIDN * KIN];       // folded W1, fp16 [N=512][K=768]
__device__ __align__(16) __half g_W2h[EDIM * HIDN];      // W2 fp16 [N=256][K=512]
__device__ __align__(16) __half g_H[(size_t)BTOT * HIDN];// hidden fp16 [131072][512]

// ============================================================================
// PTX helpers (baseline sm_80+ features only: mma.sync / ldmatrix / cp.async)
// ============================================================================
__device__ __forceinline__ uint32_t smem_u32(const void* p) {
    uint32_t a;
    asm("{ .reg .u64 t; cvta.to.shared.u64 t, %1; cvt.u32.u64 %0, t; }" : "=r"(a) : "l"(p));
    return a;
}

__device__ __forceinline__ void cp_async16(uint32_t saddr, const void* gaddr) {
    asm volatile("cp.async.cg.shared.global [%0], [%1], 16;" :: "r"(saddr), "l"(gaddr));
}
__device__ __forceinline__ void cp_commit() { asm volatile("cp.async.commit_group;" ::: "memory"); }
__device__ __forceinline__ void cp_wait0()  { asm volatile("cp.async.wait_group 0;" ::: "memory"); }

__device__ __forceinline__ void ldm_x4(uint32_t& r0, uint32_t& r1, uint32_t& r2, uint32_t& r3,
                                       uint32_t addr) {
    asm volatile("ldmatrix.sync.aligned.m8n8.x4.shared.b16 {%0,%1,%2,%3}, [%4];"
                 : "=r"(r0), "=r"(r1), "=r"(r2), "=r"(r3) : "r"(addr));
}

__device__ __forceinline__ void mma16816(float* c, uint32_t a0, uint32_t a1, uint32_t a2,
                                         uint32_t a3, uint32_t b0, uint32_t b1) {
    asm volatile(
        "mma.sync.aligned.m16n8k16.row.col.f32.f16.f16.f32 "
        "{%0,%1,%2,%3}, {%4,%5,%6,%7}, {%8,%9}, {%0,%1,%2,%3};"
        : "+f"(c[0]), "+f"(c[1]), "+f"(c[2]), "+f"(c[3])
        : "r"(a0), "r"(a1), "r"(a2), "r"(a3), "r"(b0), "r"(b1));
}

// XOR swizzle for a [128 rows][64 halves] tile (128B rows, 16B units, 8-way)
__device__ __forceinline__ uint32_t swz(uint32_t row, uint32_t k) {
    return row * 128u + ((((k >> 3) ^ (row & 7)) << 4) | ((k & 7) * 2u));
}

// ============================================================================
// Precompute kernels
// ============================================================================

// zero g_M (atomic-accumulated): 393216 floats = 98304 float4, grid 384
__global__ void k_zero() {
    size_t i = (size_t)blockIdx.x * 256 + threadIdx.x;
    float4 z = {0.f, 0.f, 0.f, 0.f};
    ((float4*)g_M)[i] = z;
}

// W1, W2 -> fp16 (grid 2048: 1536 for W1, 512 for W2)
__global__ void k_h16(const float* __restrict__ W1, const float* __restrict__ W2) {
    int bi = blockIdx.x;
    if (bi < 1536) {
        int idx = bi * 256 + threadIdx.x;
        g_W1h[idx] = __float2half_rn(W1[idx]);
    } else {
        int idx = (bi - 1536) * 256 + threadIdx.x;
        g_W2h[idx] = __float2half_rn(W2[idx]);
    }
}

// M_i = Wo_i @ Wv_i, split-K x2 (R9 proven): grid (4, 4, 12)
__global__ void __launch_bounds__(256) k_M(const float* __restrict__ Wo,
                                           const float* __restrict__ Wv) {
    const int z  = blockIdx.z;
    const int i  = z >> 1;
    const int mbase = (z & 1) * 128;
    const int k0 = blockIdx.x * 64, e0 = blockIdx.y * 64;
    const int tid = threadIdx.x;
    __shared__ float sA[64][17];
    __shared__ float sB[16][65];
    const float* A  = Wo + i * 65536;
    const float* Bm = Wv + i * 65536;
    float acc[4][4] = {};
    const int ty = tid >> 4, tx = tid & 15;
    for (int m0 = mbase; m0 < mbase + 128; m0 += 16) {
        {
            int e = tid >> 4, mm = tid & 15;
#pragma unroll
            for (int r = 0; r < 4; r++)
                sA[r * 16 + e][mm] = A[(e0 + r * 16 + e) * 256 + m0 + mm];
        }
        {
            int mm = tid >> 6, kk = tid & 63;
#pragma unroll
            for (int r = 0; r < 4; r++)
                sB[r * 4 + mm][kk] = Bm[(m0 + r * 4 + mm) * 256 + k0 + kk];
        }
        __syncthreads();
#pragma unroll
        for (int kk = 0; kk < 16; kk++) {
            float a[4], b[4];
#pragma unroll
            for (int x = 0; x < 4; x++) a[x] = sA[ty * 4 + x][kk];
#pragma unroll
            for (int x = 0; x < 4; x++) b[x] = sB[kk][tx * 4 + x];
#pragma unroll
            for (int x = 0; x < 4; x++)
#pragma unroll
                for (int y = 0; y < 4; y++) acc[x][y] += a[x] * b[y];
        }
        __syncthreads();
    }
#pragma unroll
    for (int x = 0; x < 4; x++)
#pragma unroll
        for (int y = 0; y < 4; y++)
            atomicAdd(&g_M[i * 65536 + (e0 + ty * 4 + x) * 256 + k0 + tx * 4 + y], acc[x][y]);
}

// c_i = Wo_i @ bv_i + bo_i
__global__ void k_cvec(const float* __restrict__ Wo, const float* __restrict__ bv,
                       const float* __restrict__ bo) {
    int i = blockIdx.x, e = threadIdx.x;
    const float* w = Wo + i * 65536 + e * 256;
    const float* b = bv + i * 256;
    float a0 = 0.f, a1 = 0.f, a2 = 0.f, a3 = 0.f;
#pragma unroll 4
    for (int m = 0; m < 256; m += 4) {
        a0 += w[m + 0] * b[m + 0];
        a1 += w[m + 1] * b[m + 1];
        a2 += w[m + 2] * b[m + 2];
        a3 += w[m + 3] * b[m + 3];
    }
    g_cvec[i * 256 + e] = bo[i * 256 + e] + (a0 + a1) + (a2 + a3);
}

// repack: g_Bc[r][kp][qi*256+e] = fp16(g_M[midx(r,qi)][e][kp])
// grid 1536 x 256: t = global idx over 393216; e=t&255, qi=(t>>8)&1, kp=(t>>9)&255, r=t>>17
__global__ void k_Bc() {
    int t = blockIdx.x * 256 + threadIdx.x;
    int e  = t & 255;
    int qi = (t >> 8) & 1;
    int kp = (t >> 9) & 255;
    int r  = t >> 17;
    // q = qi-th element of {0,1,2}\{r}; midx table (r,q): (0,1)->2 (0,2)->4 (1,0)->0 (1,2)->5 (2,0)->1 (2,1)->3
    int midx = (r == 0) ? (qi == 0 ? 2 : 4)
             : (r == 1) ? (qi == 0 ? 0 : 5)
                        : (qi == 0 ? 1 : 3);
    g_Bc[r * 131072 + kp * 512 + qi * 256 + e] = __float2half_rn(g_M[midx * 65536 + e * 256 + kp]);
}

// b1eff[n] = b1[n] + sum_j csum[j] * W1[n][j]
__global__ void __launch_bounds__(256) k_b1eff(const float* __restrict__ W1,
                                               const float* __restrict__ b1) {
    const int n = blockIdx.x;
    const int tid = threadIdx.x;
    float p = 0.f;
#pragma unroll
    for (int jj = 0; jj < 3; jj++) {
        int j = jj * 256 + tid;
        int q = j >> 8, e = j & 255;
        float cs = g_cvec[(2 * q) * 256 + e] + g_cvec[(2 * q + 1) * 256 + e];
        p += cs * W1[n * KIN + j];
    }
    __shared__ float red[256];
    red[tid] = p;
    __syncthreads();
#pragma unroll
    for (int s = 128; s > 0; s >>= 1) {
        if (tid < s) red[tid] += red[tid + s];
        __syncthreads();
    }
    if (tid == 0) g_b1eff[n] = b1[n] + red[0];
}

// ============================================================================
// SMEM layout shared by all mma kernels
// ============================================================================
#define SM_A0 0
#define SM_A1 16384
#define SM_B0 32768
#define SM_B1 49152
#define SMEM_G 65536

// ============================================================================
// k_B1mma: per r, fold[n][kp] = W1h[n, qe-sel] @ Bc[r]^T ; epilogue adds W1 fp32
// grid (2 kp-chunks, 4 n-chunks, 3 r); M=512(n) N=256(kp) K=512(qe)
// ============================================================================
__global__ void __launch_bounds__(256, 2)
k_B1mma(const float* __restrict__ W1) {
    extern __shared__ char smem[];
    const uint32_t sb = smem_u32(smem);
    const int tid = threadIdx.x;
    const int wid = tid >> 5, lane = tid & 31;
    const int m0 = blockIdx.y * 128;        // n-dim (rows of W1)
    const int n0 = blockIdx.x * 128;        // kp-dim
    const int r  = blockIdx.z;
    const int wm = (wid >> 2) * 64;
    const int wn = (wid & 3) * 32;
    const int q0 = (r == 0) ? 1 : 0;
    const int q1 = (r == 2) ? 1 : 2;
    const __half* Bsrc = g_Bc + r * 131072;

    float acc[4][4][4];
#pragma unroll
    for (int i = 0; i < 4; i++)
#pragma unroll
        for (int j = 0; j < 4; j++)
#pragma unroll
            for (int v = 0; v < 4; v++) acc[i][j][v] = 0.f;

    // prologue: buffer 0 (kc = 0 -> q = q0, colpart 0)
    {
#pragma unroll
        for (int i = 0; i < 4; i++) {
            int idx = i * 256 + tid;
            int row = idx >> 3, c = idx & 7;
            cp_async16(sb + SM_A0 + swz(row, c * 8),
                       g_W1h + (size_t)(m0 + row) * KIN + q0 * 256 + c * 8);
            cp_async16(sb + SM_B0 + swz(row, c * 8),
                       Bsrc + (size_t)(n0 + row) * 512 + c * 8);
        }
        cp_commit();
        cp_wait0();
        __syncthreads();
    }

    const int NITER = 8;
    for (int kc = 0; kc < NITER; kc++) {
        const uint32_t Abase = sb + (kc & 1 ? SM_A1 : SM_A0);
        const uint32_t Bbase = sb + (kc & 1 ? SM_B1 : SM_B0);
        const int nxt = kc + 1;

        if (nxt < NITER) {
            uint32_t AbaseN = sb + (nxt & 1 ? SM_A1 : SM_A0);
            uint32_t BbaseN = sb + (nxt & 1 ? SM_B1 : SM_B0);
            int q = (nxt >> 2) ? q1 : q0;
            int colbase = q * 256 + (nxt & 3) * 64;
#pragma unroll
            for (int i = 0; i < 4; i++) {
                int idx = i * 256 + tid;
                int row = idx >> 3, c = idx & 7;
                cp_async16(AbaseN + swz(row, c * 8),
                           g_W1h + (size_t)(m0 + row) * KIN + colbase + c * 8);
                cp_async16(BbaseN + swz(row, c * 8),
                           Bsrc + (size_t)(n0 + row) * 512 + nxt * 64 + c * 8);
            }
            cp_commit();
        }

#pragma unroll
        for (int ks = 0; ks < 64; ks += 16) {
            uint32_t a[4][4], b[8];
#pragma unroll
            for (int t = 0; t < 4; t++) {
                uint32_t row = wm + t * 16 + (lane & 15);
                uint32_t kk  = ks + (lane >> 4) * 8;
                ldm_x4(a[t][0], a[t][1], a[t][2], a[t][3], Abase + swz(row, kk));
            }
#pragma unroll
            for (int h = 0; h < 2; h++) {
                int g = lane >> 3, ri = lane & 7;
                uint32_t nrow = wn + h * 16 + (g >> 1) * 8 + ri;
                uint32_t kk   = ks + (g & 1) * 8;
                ldm_x4(b[h * 4 + 0], b[h * 4 + 1], b[h * 4 + 2], b[h * 4 + 3],
                       Bbase + swz(nrow, kk));
            }
#pragma unroll
            for (int mt = 0; mt < 4; mt++)
#pragma unroll
                for (int nt = 0; nt < 4; nt++)
                    mma16816(acc[mt][nt], a[mt][0], a[mt][1], a[mt][2], a[mt][3],
                             b[nt * 2], b[nt * 2 + 1]);
        }

        if (nxt < NITER) cp_wait0();
        __syncthreads();
    }

    // epilogue: B1h[n][r*256+kp] = fp16(W1[n][r*256+kp] + acc)
#pragma unroll
    for (int mt = 0; mt < 4; mt++) {
#pragma unroll
        for (int nt = 0; nt < 4; nt++) {
            int kp = n0 + wn + nt * 8 + (lane & 3) * 2;
            int nrow0 = m0 + wm + mt * 16 + (lane >> 2);
            size_t base0 = (size_t)nrow0 * KIN + r * 256 + kp;
            size_t base1 = (size_t)(nrow0 + 8) * KIN + r * 256 + kp;
            __half2 h01 = __floats2half2_rn(W1[base0] + acc[mt][nt][0],
                                            W1[base0 + 1] + acc[mt][nt][1]);
            __half2 h23 = __floats2half2_rn(W1[base1] + acc[mt][nt][2],
                                            W1[base1 + 1] + acc[mt][nt][3]);
            *(__half2*)(g_B1h + base0) = h01;
            *(__half2*)(g_B1h + base1) = h23;
        }
    }
}

// ============================================================================
// GEMM1 (R6 winner): hidden[B,512] = relu(X[B,768] @ B1h^T + b1eff)
// 256 thr, tile 128x128, warp tile 64x32, K-chunk 64, double-buffered, occ 2
// ============================================================================
__global__ void __launch_bounds__(256, 2)
gemm1(const float* __restrict__ gE, const float* __restrict__ dE,
      const float* __restrict__ cE) {
    extern __shared__ char smem[];
    const uint32_t sb = smem_u32(smem);
    const int tid = threadIdx.x;
    const int wid = tid >> 5, lane = tid & 31;
    const int m0 = blockIdx.y * 128;
    const int n0 = blockIdx.x * 128;
    const int wm = (wid >> 2) * 64;
    const int wn = (wid & 3) * 32;
    const float* srcs[3] = {gE, dE, cE};

    float acc[4][4][4];
#pragma unroll
    for (int i = 0; i < 4; i++)
#pragma unroll
        for (int j = 0; j < 4; j++)
#pragma unroll
            for (int v = 0; v < 4; v++) acc[i][j][v] = 0.f;

    const int a_row[8] = { (0*256+tid) >> 4, (1*256+tid) >> 4, (2*256+tid) >> 4, (3*256+tid) >> 4,
                           (4*256+tid) >> 4, (5*256+tid) >> 4, (6*256+tid) >> 4, (7*256+tid) >> 4 };
    const int a_c4 = tid & 15;

    uint2 ah[8];   // A fragment converted to fp16 at load time

    // prologue: buffer 0 (kc = 0)
    {
        const float* src = srcs[0] + (size_t)m0 * 256;
#pragma unroll
        for (int i = 0; i < 8; i++) {
            float4 f = *(const float4*)(src + (size_t)a_row[i] * 256 + a_c4 * 4);
            __half2 h0 = __floats2half2_rn(f.x, f.y);
            __half2 h1 = __floats2half2_rn(f.z, f.w);
            ah[i].x = *(uint32_t*)&h0;
            ah[i].y = *(uint32_t*)&h1;
        }
#pragma unroll
        for (int i = 0; i < 8; i++)
            *(uint2*)(smem + SM_A0 + swz(a_row[i], a_c4 * 4)) = ah[i];
#pragma unroll
        for (int i = 0; i < 4; i++) {
            int idx = i * 256 + tid;
            int row = idx >> 3, c = idx & 7;
            cp_async16(sb + SM_B0 + swz(row, c * 8), g_B1h + (size_t)(n0 + row) * KIN + c * 8);
        }
        cp_commit();
        cp_wait0();
        __syncthreads();
    }

    const int NITER = 12;
    for (int kc = 0; kc < NITER; kc++) {
        const uint32_t Abase = sb + (kc & 1 ? SM_A1 : SM_A0);
        const uint32_t Bbase = sb + (kc & 1 ? SM_B1 : SM_B0);
        const int nxt = kc + 1;
        const uint32_t AbaseN = sb + (nxt & 1 ? SM_A1 : SM_A0);
        const uint32_t BbaseN = sb + (nxt & 1 ? SM_B1 : SM_B0);

        if (nxt < NITER) {
            const float* src = srcs[nxt >> 2] + (size_t)m0 * 256 + (nxt & 3) * 64;
#pragma unroll
            for (int i = 0; i < 8; i++) {
                float4 f = *(const float4*)(src + (size_t)a_row[i] * 256 + a_c4 * 4);
                __half2 h0 = __floats2half2_rn(f.x, f.y);
                __half2 h1 = __floats2half2_rn(f.z, f.w);
                ah[i].x = *(uint32_t*)&h0;
                ah[i].y = *(uint32_t*)&h1;
            }
#pragma unroll
            for (int i = 0; i < 4; i++) {
                int idx = i * 256 + tid;
                int row = idx >> 3, c = idx & 7;
                cp_async16(BbaseN + swz(row, c * 8),
                           g_B1h + (size_t)(n0 + row) * KIN + nxt * 64 + c * 8);
            }
            cp_commit();
        }

        // compute on current buffers
#pragma unroll
        for (int ks = 0; ks < 64; ks += 16) {
            uint32_t a[4][4], b[8];
#pragma unroll
            for (int t = 0; t < 4; t++) {
                uint32_t row = wm + t * 16 + (lane & 15);
                uint32_t kk  = ks + (lane >> 4) * 8;
                ldm_x4(a[t][0], a[t][1], a[t][2], a[t][3], Abase + swz(row, kk));
            }
#pragma unroll
            for (int h = 0; h < 2; h++) {
                int g = lane >> 3, ri = lane & 7;
                uint32_t nrow = wn + h * 16 + (g >> 1) * 8 + ri;
                uint32_t kk   = ks + (g & 1) * 8;
                ldm_x4(b[h * 4 + 0], b[h * 4 + 1], b[h * 4 + 2], b[h * 4 + 3],
                       Bbase + swz(nrow, kk));
            }
#pragma unroll
            for (int mt = 0; mt < 4; mt++)
#pragma unroll
                for (int nt = 0; nt < 4; nt++)
                    mma16816(acc[mt][nt], a[mt][0], a[mt][1], a[mt][2], a[mt][3],
                             b[nt * 2], b[nt * 2 + 1]);
        }

        if (nxt < NITER) {
#pragma unroll
            for (int i = 0; i < 8; i++)
                *(uint2*)((char*)smem + (AbaseN - sb) + swz(a_row[i], a_c4 * 4)) = ah[i];
            cp_wait0();
        }
        __syncthreads();
    }

    // epilogue: relu(acc + b1eff) -> fp16 g_H
#pragma unroll
    for (int mt = 0; mt < 4; mt++) {
#pragma unroll
        for (int nt = 0; nt < 4; nt++) {
            int n = n0 + wn + nt * 8 + (lane & 3) * 2;
            float bia0 = g_b1eff[n], bia1 = g_b1eff[n + 1];
            int r0 = m0 + wm + mt * 16 + (lane >> 2);
            float v0 = fmaxf(acc[mt][nt][0] + bia0, 0.f);
            float v1 = fmaxf(acc[mt][nt][1] + bia1, 0.f);
            float v2 = fmaxf(acc[mt][nt][2] + bia0, 0.f);
            float v3 = fmaxf(acc[mt][nt][3] + bia1, 0.f);
            __half2 h01 = __floats2half2_rn(v0, v1);
            __half2 h23 = __floats2half2_rn(v2, v3);
            *(__half2*)(g_H + (size_t)r0 * HIDN + n)       = h01;
            *(__half2*)(g_H + (size_t)(r0 + 8) * HIDN + n) = h23;
        }
    }
}

// ============================================================================
// GEMM2 (R6 winner): out[B,256] = g_H[B,512] @ W2h^T + b2, fp32 out, occ 2
// ============================================================================
__global__ void __launch_bounds__(256, 2)
gemm2(const float* __restrict__ b2, float* __restrict__ out) {
    extern __shared__ char smem[];
    const uint32_t sb = smem_u32(smem);
    const int tid = threadIdx.x;
    const int wid = tid >> 5, lane = tid & 31;
    const int m0 = blockIdx.y * 128;
    const int n0 = blockIdx.x * 128;
    const int wm = (wid >> 2) * 64;
    const int wn = (wid & 3) * 32;

    float acc[4][4][4];
#pragma unroll
    for (int i = 0; i < 4; i++)
#pragma unroll
        for (int j = 0; j < 4; j++)
#pragma unroll
            for (int v = 0; v < 4; v++) acc[i][j][v] = 0.f;

    // prologue buffer 0
    {
#pragma unroll
        for (int i = 0; i < 4; i++) {
            int idx = i * 256 + tid;
            int row = idx >> 3, c = idx & 7;
            cp_async16(sb + SM_A0 + swz(row, c * 8), g_H + (size_t)(m0 + row) * HIDN + c * 8);
            cp_async16(sb + SM_B0 + swz(row, c * 8), g_W2h + (size_t)(n0 + row) * HIDN + c * 8);
        }
        cp_commit();
        cp_wait0();
        __syncthreads();
    }

    const int NITER = 8;
    for (int kc = 0; kc < NITER; kc++) {
        const uint32_t Abase = sb + (kc & 1 ? SM_A1 : SM_A0);
        const uint32_t Bbase = sb + (kc & 1 ? SM_B1 : SM_B0);
        const int nxt = kc + 1;

        if (nxt < NITER) {
            uint32_t AbaseN = sb + (nxt & 1 ? SM_A1 : SM_A0);
            uint32_t BbaseN = sb + (nxt & 1 ? SM_B1 : SM_B0);
#pragma unroll
            for (int i = 0; i < 4; i++) {
                int idx = i * 256 + tid;
                int row = idx >> 3, c = idx & 7;
                cp_async16(AbaseN + swz(row, c * 8),
                           g_H + (size_t)(m0 + row) * HIDN + nxt * 64 + c * 8);
                cp_async16(BbaseN + swz(row, c * 8),
                           g_W2h + (size_t)(n0 + row) * HIDN + nxt * 64 + c * 8);
            }
            cp_commit();
        }

#pragma unroll
        for (int ks = 0; ks < 64; ks += 16) {
            uint32_t a[4][4], b[8];
#pragma unroll
            for (int t = 0; t < 4; t++) {
                uint32_t row = wm + t * 16 + (lane & 15);
                uint32_t kk  = ks + (lane >> 4) * 8;
                ldm_x4(a[t][0], a[t][1], a[t][2], a[t][3], Abase + swz(row, kk));
            }
#pragma unroll
            for (int h = 0; h < 2; h++) {
                int g = lane >> 3, ri = lane & 7;
                uint32_t nrow = wn + h * 16 + (g >> 1) * 8 + ri;
                uint32_t kk   = ks + (g & 1) * 8;
                ldm_x4(b[h * 4 + 0], b[h * 4 + 1], b[h * 4 + 2], b[h * 4 + 3],
                       Bbase + swz(nrow, kk));
            }
#pragma unroll
            for (int mt = 0; mt < 4; mt++)
#pragma unroll
                for (int nt = 0; nt < 4; nt++)
                    mma16816(acc[mt][nt], a[mt][0], a[mt][1], a[mt][2], a[mt][3],
                             b[nt * 2], b[nt * 2 + 1]);
        }

        if (nxt < NITER) cp_wait0();
        __syncthreads();
    }

    // epilogue: acc + b2 -> fp32 out
#pragma unroll
    for (int mt = 0; mt < 4; mt++) {
#pragma unroll
        for (int nt = 0; nt < 4; nt++) {
            int n = n0 + wn + nt * 8 + (lane & 3) * 2;
            float bia0 = b2[n], bia1 = b2[n + 1];
            int r0 = m0 + wm + mt * 16 + (lane >> 2);
            float2 o01 = { acc[mt][nt][0] + bia0, acc[mt][nt][1] + bia1 };
            float2 o23 = { acc[mt][nt][2] + bia0, acc[mt][nt][3] + bia1 };
            *(float2*)(out + (size_t)r0 * EDIM + n)       = o01;
            *(float2*)(out + (size_t)(r0 + 8) * EDIM + n) = o23;
        }
    }
}

// ============================================================================
// kernel_launch
// Input order: g, d, c, Wq, Wk, Wv, bq, bk, bv, Wo, bo, W1, b1, W2, b2
// ============================================================================
extern "C" void kernel_launch(void* const* d_in, const int* in_sizes, int n_in,
                              void* d_out, int out_size) {
    const float* g  = (const float*)d_in[0];
    const float* dd = (const float*)d_in[1];
    const float* cc = (const float*)d_in[2];
    const float* Wv = (const float*)d_in[5];
    const float* bv = (const float*)d_in[8];
    const float* Wo = (const float*)d_in[9];
    const float* bo = (const float*)d_in[10];
    const float* W1 = (const float*)d_in[11];
    const float* b1 = (const float*)d_in[12];
    const float* W2 = (const float*)d_in[13];
    const float* b2 = (const float*)d_in[14];
    const int B = in_sizes[0] / EDIM;

    cudaFuncSetAttribute(k_B1mma, cudaFuncAttributeMaxDynamicSharedMemorySize, SMEM_G);
    cudaFuncSetAttribute(gemm1,   cudaFuncAttributeMaxDynamicSharedMemorySize, SMEM_G);
    cudaFuncSetAttribute(gemm2,   cudaFuncAttributeMaxDynamicSharedMemorySize, SMEM_G);

    // Precompute chain (critical path ~30us):
    k_zero  <<<384, 256>>>();                     // g_M = 0
    k_cvec  <<<6, 256>>>(Wo, bv, bo);
    k_h16   <<<2048, 256>>>(W1, W2);              // W1h, W2h
    k_M     <<<dim3(4, 4, 12), 256>>>(Wo, Wv);    // split-K x2 (R9 proven)
    k_Bc    <<<1536, 256>>>();                    // M -> fp16 transposed+packed
    k_B1mma <<<dim3(2, 4, 3), 256, SMEM_G>>>(W1); // tensor-core fold (+W1, ->fp16)
    k_b1eff <<<HIDN, 256>>>(W1, b1);

    gemm1<<<dim3(4, B / 128), 256, SMEM_G>>>(g, dd, cc);
    gemm2<<<dim3(2, B / 128), 256, SMEM_G>>>(b2, (float*)d_out);
}

// round 12
// speedup vs baseline: 1.0453x; 1.0272x over previous
#include <cuda_runtime.h>
#include <cuda_fp16.h>
#include <cstdint>

// ============================================================================
// Problem constants
// ============================================================================
#define EDIM 256      // E
#define HIDN 512      // 2E
#define KIN  768      // 3E
#define BTOT 131072

// ============================================================================
// Device scratch (allocation-free rule: __device__ globals)
// ============================================================================
__device__ float  g_cvec[6 * EDIM];                      // c_i = Wo_i @ bv_i + bo_i
__device__ float  g_b1eff[HIDN];                         // b1 + Kvec @ W1^T
__device__ __align__(16) __half g_W1h[HIDN * KIN];       // W1 fp16
__device__ __align__(16) __half g_Woh[6 * EDIM * EDIM];  // Wo fp16 [i][e][m]
__device__ __align__(16) __half g_Wvt[6 * EDIM * EDIM];  // Wv fp16 transposed [i][kp][m]
__device__ __align__(16) __half g_Bc[3 * EDIM * HIDN];   // repacked M: [r][kp][qe] fp16
__device__ __align__(16) __half g_B1h[HIDN * KIN];       // folded W1, fp16 [N=512][K=768]
__device__ __align__(16) __half g_W2h[EDIM * HIDN];      // W2 fp16 [N=256][K=512]
__device__ __align__(16) __half g_H[(size_t)BTOT * HIDN];// hidden fp16 [131072][512]

// ============================================================================
// PTX helpers (baseline sm_80+ features only: mma.sync / ldmatrix / cp.async)
// ============================================================================
__device__ __forceinline__ uint32_t smem_u32(const void* p) {
    uint32_t a;
    asm("{ .reg .u64 t; cvta.to.shared.u64 t, %1; cvt.u32.u64 %0, t; }" : "=r"(a) : "l"(p));
    return a;
}

__device__ __forceinline__ void cp_async16(uint32_t saddr, const void* gaddr) {
    asm volatile("cp.async.cg.shared.global [%0], [%1], 16;" :: "r"(saddr), "l"(gaddr));
}
__device__ __forceinline__ void cp_commit() { asm volatile("cp.async.commit_group;" ::: "memory"); }
__device__ __forceinline__ void cp_wait0()  { asm volatile("cp.async.wait_group 0;" ::: "memory"); }

__device__ __forceinline__ void ldm_x4(uint32_t& r0, uint32_t& r1, uint32_t& r2, uint32_t& r3,
                                       uint32_t addr) {
    asm volatile("ldmatrix.sync.aligned.m8n8.x4.shared.b16 {%0,%1,%2,%3}, [%4];"
                 : "=r"(r0), "=r"(r1), "=r"(r2), "=r"(r3) : "r"(addr));
}

__device__ __forceinline__ void mma16816(float* c, uint32_t a0, uint32_t a1, uint32_t a2,
                                         uint32_t a3, uint32_t b0, uint32_t b1) {
    asm volatile(
        "mma.sync.aligned.m16n8k16.row.col.f32.f16.f16.f32 "
        "{%0,%1,%2,%3}, {%4,%5,%6,%7}, {%8,%9}, {%0,%1,%2,%3};"
        : "+f"(c[0]), "+f"(c[1]), "+f"(c[2]), "+f"(c[3])
        : "r"(a0), "r"(a1), "r"(a2), "r"(a3), "r"(b0), "r"(b1));
}

// XOR swizzle for a [128 rows][64 halves] tile (128B rows, 16B units, 8-way)
__device__ __forceinline__ uint32_t swz(uint32_t row, uint32_t k) {
    return row * 128u + ((((k >> 3) ^ (row & 7)) << 4) | ((k & 7) * 2u));
}

// ============================================================================
// Precompute kernels
// ============================================================================

// W1, W2, Wo -> fp16 (grid 3584: [0,1536) W1, [1536,2048) W2, [2048,3584) Wo)
__global__ void k_h16(const float* __restrict__ W1, const float* __restrict__ W2,
                      const float* __restrict__ Wo) {
    int bi = blockIdx.x;
    if (bi < 1536) {
        int idx = bi * 256 + threadIdx.x;
        g_W1h[idx] = __float2half_rn(W1[idx]);
    } else if (bi < 2048) {
        int idx = (bi - 1536) * 256 + threadIdx.x;
        g_W2h[idx] = __float2half_rn(W2[idx]);
    } else {
        int idx = (bi - 2048) * 256 + threadIdx.x;
        g_Woh[idx] = __float2half_rn(Wo[idx]);
    }
}

// Wv [i][m][kp] -> g_Wvt [i][kp][m] fp16, 32x32 smem tiles. grid (8,8,6), block (32,8)
__global__ void k_wt(const float* __restrict__ Wv) {
    __shared__ float t[32][33];
    const int i = blockIdx.z;
    const int m0 = blockIdx.x * 32, kp0 = blockIdx.y * 32;
    const float* src = Wv + i * 65536;
#pragma unroll
    for (int j = 0; j < 4; j++) {
        int row = threadIdx.y + j * 8;
        t[row][threadIdx.x] = src[(m0 + row) * 256 + kp0 + threadIdx.x];
    }
    __syncthreads();
#pragma unroll
    for (int j = 0; j < 4; j++) {
        int row = threadIdx.y + j * 8;   // kp-local
        g_Wvt[i * 65536 + (kp0 + row) * 256 + m0 + threadIdx.x] =
            __float2half_rn(t[threadIdx.x][row]);
    }
}

// c_i = Wo_i @ bv_i + bo_i
__global__ void k_cvec(const float* __restrict__ Wo, const float* __restrict__ bv,
                       const float* __restrict__ bo) {
    int i = blockIdx.x, e = threadIdx.x;
    const float* w = Wo + i * 65536 + e * 256;
    const float* b = bv + i * 256;
    float a0 = 0.f, a1 = 0.f, a2 = 0.f, a3 = 0.f;
#pragma unroll 4
    for (int m = 0; m < 256; m += 4) {
        a0 += w[m + 0] * b[m + 0];
        a1 += w[m + 1] * b[m + 1];
        a2 += w[m + 2] * b[m + 2];
        a3 += w[m + 3] * b[m + 3];
    }
    g_cvec[i * 256 + e] = bo[i * 256 + e] + (a0 + a1) + (a2 + a3);
}

// b1eff[n] = b1[n] + sum_j csum[j] * W1[n][j]
__global__ void __launch_bounds__(256) k_b1eff(const float* __restrict__ W1,
                                               const float* __restrict__ b1) {
    const int n = blockIdx.x;
    const int tid = threadIdx.x;
    float p = 0.f;
#pragma unroll
    for (int jj = 0; jj < 3; jj++) {
        int j = jj * 256 + tid;
        int q = j >> 8, e = j & 255;
        float cs = g_cvec[(2 * q) * 256 + e] + g_cvec[(2 * q + 1) * 256 + e];
        p += cs * W1[n * KIN + j];
    }
    __shared__ float red[256];
    red[tid] = p;
    __syncthreads();
#pragma unroll
    for (int s = 128; s > 0; s >>= 1) {
        if (tid < s) red[tid] += red[tid + s];
        __syncthreads();
    }
    if (tid == 0) g_b1eff[n] = b1[n] + red[0];
}

// ============================================================================
// SMEM layout shared by all mma kernels
// ============================================================================
#define SM_A0 0
#define SM_A1 16384
#define SM_B0 32768
#define SM_B1 49152
#define SMEM_G 65536

// ============================================================================
// k_Mmma: M_i[e][kp] = Woh_i[e][:] @ Wvt_i[kp][:]  (M=256, N=256, K=256)
// grid (2 kp-chunks, 2 e-chunks, 6 i); epilogue writes g_Bc[r][kp][qi*256+e] fp16
// ============================================================================
__global__ void __launch_bounds__(256, 2)
k_Mmma() {
    extern __shared__ char smem[];
    const uint32_t sb = smem_u32(smem);
    const int tid = threadIdx.x;
    const int wid = tid >> 5, lane = tid & 31;
    const int i  = blockIdx.z;
    const int e0c  = blockIdx.y * 128;      // e-chunk (rows of A)
    const int kp0c = blockIdx.x * 128;      // kp-chunk
    const int wm = (wid >> 2) * 64;
    const int wn = (wid & 3) * 32;
    // inverse of midx table: i -> (r, qi)
    // midx 0->(1,0) 1->(2,0) 2->(0,0) 3->(2,1) 4->(0,1) 5->(1,1)
    const int r  = (i == 0) ? 1 : (i == 1) ? 2 : (i == 2) ? 0 : (i == 3) ? 2 : (i == 4) ? 0 : 1;
    const int qi = (i <= 2) ? 0 : 1;
    const __half* Asrc = g_Woh + i * 65536;
    const __half* Bsrc = g_Wvt + i * 65536;

    float acc[4][4][4];
#pragma unroll
    for (int a = 0; a < 4; a++)
#pragma unroll
        for (int j = 0; j < 4; j++)
#pragma unroll
            for (int v = 0; v < 4; v++) acc[a][j][v] = 0.f;

    // prologue buffer 0
    {
#pragma unroll
        for (int a = 0; a < 4; a++) {
            int idx = a * 256 + tid;
            int row = idx >> 3, c = idx & 7;
            cp_async16(sb + SM_A0 + swz(row, c * 8), Asrc + (size_t)(e0c + row) * 256 + c * 8);
            cp_async16(sb + SM_B0 + swz(row, c * 8), Bsrc + (size_t)(kp0c + row) * 256 + c * 8);
        }
        cp_commit();
        cp_wait0();
        __syncthreads();
    }

    const int NITER = 4;
    for (int kc = 0; kc < NITER; kc++) {
        const uint32_t Abase = sb + (kc & 1 ? SM_A1 : SM_A0);
        const uint32_t Bbase = sb + (kc & 1 ? SM_B1 : SM_B0);
        const int nxt = kc + 1;

        if (nxt < NITER) {
            uint32_t AbaseN = sb + (nxt & 1 ? SM_A1 : SM_A0);
            uint32_t BbaseN = sb + (nxt & 1 ? SM_B1 : SM_B0);
#pragma unroll
            for (int a = 0; a < 4; a++) {
                int idx = a * 256 + tid;
                int row = idx >> 3, c = idx & 7;
                cp_async16(AbaseN + swz(row, c * 8),
                           Asrc + (size_t)(e0c + row) * 256 + nxt * 64 + c * 8);
                cp_async16(BbaseN + swz(row, c * 8),
                           Bsrc + (size_t)(kp0c + row) * 256 + nxt * 64 + c * 8);
            }
            cp_commit();
        }

#pragma unroll
        for (int ks = 0; ks < 64; ks += 16) {
            uint32_t a[4][4], b[8];
#pragma unroll
            for (int t = 0; t < 4; t++) {
                uint32_t row = wm + t * 16 + (lane & 15);
                uint32_t kk  = ks + (lane >> 4) * 8;
                ldm_x4(a[t][0], a[t][1], a[t][2], a[t][3], Abase + swz(row, kk));
            }
#pragma unroll
            for (int h = 0; h < 2; h++) {
                int g = lane >> 3, ri = lane & 7;
                uint32_t nrow = wn + h * 16 + (g >> 1) * 8 + ri;
                uint32_t kk   = ks + (g & 1) * 8;
                ldm_x4(b[h * 4 + 0], b[h * 4 + 1], b[h * 4 + 2], b[h * 4 + 3],
                       Bbase + swz(nrow, kk));
            }
#pragma unroll
            for (int mt = 0; mt < 4; mt++)
#pragma unroll
                for (int nt = 0; nt < 4; nt++)
                    mma16816(acc[mt][nt], a[mt][0], a[mt][1], a[mt][2], a[mt][3],
                             b[nt * 2], b[nt * 2 + 1]);
        }

        if (nxt < NITER) cp_wait0();
        __syncthreads();
    }

    // epilogue: g_Bc[r][kp][qi*256 + e] = fp16(M[e][kp])
    __half* dst = g_Bc + r * 131072 + qi * 256;
#pragma unroll
    for (int mt = 0; mt < 4; mt++) {
#pragma unroll
        for (int nt = 0; nt < 4; nt++) {
            int kp = kp0c + wn + nt * 8 + (lane & 3) * 2;
            int e  = e0c + wm + mt * 16 + (lane >> 2);
            dst[(size_t)kp * 512 + e]           = __float2half_rn(acc[mt][nt][0]);
            dst[(size_t)(kp + 1) * 512 + e]     = __float2half_rn(acc[mt][nt][1]);
            dst[(size_t)kp * 512 + e + 8]       = __float2half_rn(acc[mt][nt][2]);
            dst[(size_t)(kp + 1) * 512 + e + 8] = __float2half_rn(acc[mt][nt][3]);
        }
    }
}

// ============================================================================
// k_B1mma: per r, fold[n][kp] = W1h[n, qe-sel] @ Bc[r]^T ; epilogue adds W1 fp32
// grid (2 kp-chunks, 4 n-chunks, 3 r); M=512(n) N=256(kp) K=512(qe)
// ============================================================================
__global__ void __launch_bounds__(256, 2)
k_B1mma(const float* __restrict__ W1) {
    extern __shared__ char smem[];
    const uint32_t sb = smem_u32(smem);
    const int tid = threadIdx.x;
    const int wid = tid >> 5, lane = tid & 31;
    const int m0 = blockIdx.y * 128;        // n-dim (rows of W1)
    const int n0 = blockIdx.x * 128;        // kp-dim
    const int r  = blockIdx.z;
    const int wm = (wid >> 2) * 64;
    const int wn = (wid & 3) * 32;
    const int q0 = (r == 0) ? 1 : 0;
    const int q1 = (r == 2) ? 1 : 2;
    const __half* Bsrc = g_Bc + r * 131072;

    float acc[4][4][4];
#pragma unroll
    for (int i = 0; i < 4; i++)
#pragma unroll
        for (int j = 0; j < 4; j++)
#pragma unroll
            for (int v = 0; v < 4; v++) acc[i][j][v] = 0.f;

    // prologue: buffer 0 (kc = 0 -> q = q0, colpart 0)
    {
#pragma unroll
        for (int i = 0; i < 4; i++) {
            int idx = i * 256 + tid;
            int row = idx >> 3, c = idx & 7;
            cp_async16(sb + SM_A0 + swz(row, c * 8),
                       g_W1h + (size_t)(m0 + row) * KIN + q0 * 256 + c * 8);
            cp_async16(sb + SM_B0 + swz(row, c * 8),
                       Bsrc + (size_t)(n0 + row) * 512 + c * 8);
        }
        cp_commit();
        cp_wait0();
        __syncthreads();
    }

    const int NITER = 8;
    for (int kc = 0; kc < NITER; kc++) {
        const uint32_t Abase = sb + (kc & 1 ? SM_A1 : SM_A0);
        const uint32_t Bbase = sb + (kc & 1 ? SM_B1 : SM_B0);
        const int nxt = kc + 1;

        if (nxt < NITER) {
            uint32_t AbaseN = sb + (nxt & 1 ? SM_A1 : SM_A0);
            uint32_t BbaseN = sb + (nxt & 1 ? SM_B1 : SM_B0);
            int q = (nxt >> 2) ? q1 : q0;
            int colbase = q * 256 + (nxt & 3) * 64;
#pragma unroll
            for (int i = 0; i < 4; i++) {
                int idx = i * 256 + tid;
                int row = idx >> 3, c = idx & 7;
                cp_async16(AbaseN + swz(row, c * 8),
                           g_W1h + (size_t)(m0 + row) * KIN + colbase + c * 8);
                cp_async16(BbaseN + swz(row, c * 8),
                           Bsrc + (size_t)(n0 + row) * 512 + nxt * 64 + c * 8);
            }
            cp_commit();
        }

#pragma unroll
        for (int ks = 0; ks < 64; ks += 16) {
            uint32_t a[4][4], b[8];
#pragma unroll
            for (int t = 0; t < 4; t++) {
                uint32_t row = wm + t * 16 + (lane & 15);
                uint32_t kk  = ks + (lane >> 4) * 8;
                ldm_x4(a[t][0], a[t][1], a[t][2], a[t][3], Abase + swz(row, kk));
            }
#pragma unroll
            for (int h = 0; h < 2; h++) {
                int g = lane >> 3, ri = lane & 7;
                uint32_t nrow = wn + h * 16 + (g >> 1) * 8 + ri;
                uint32_t kk   = ks + (g & 1) * 8;
                ldm_x4(b[h * 4 + 0], b[h * 4 + 1], b[h * 4 + 2], b[h * 4 + 3],
                       Bbase + swz(nrow, kk));
            }
#pragma unroll
            for (int mt = 0; mt < 4; mt++)
#pragma unroll
                for (int nt = 0; nt < 4; nt++)
                    mma16816(acc[mt][nt], a[mt][0], a[mt][1], a[mt][2], a[mt][3],
                             b[nt * 2], b[nt * 2 + 1]);
        }

        if (nxt < NITER) cp_wait0();
        __syncthreads();
    }

    // epilogue: B1h[n][r*256+kp] = fp16(W1[n][r*256+kp] + acc)
#pragma unroll
    for (int mt = 0; mt < 4; mt++) {
#pragma unroll
        for (int nt = 0; nt < 4; nt++) {
            int kp = n0 + wn + nt * 8 + (lane & 3) * 2;
            int nrow0 = m0 + wm + mt * 16 + (lane >> 2);
            size_t base0 = (size_t)nrow0 * KIN + r * 256 + kp;
            size_t base1 = (size_t)(nrow0 + 8) * KIN + r * 256 + kp;
            __half2 h01 = __floats2half2_rn(W1[base0] + acc[mt][nt][0],
                                            W1[base0 + 1] + acc[mt][nt][1]);
            __half2 h23 = __floats2half2_rn(W1[base1] + acc[mt][nt][2],
                                            W1[base1 + 1] + acc[mt][nt][3]);
            *(__half2*)(g_B1h + base0) = h01;
            *(__half2*)(g_B1h + base1) = h23;
        }
    }
}

// ============================================================================
// GEMM1 (R6 winner): hidden[B,512] = relu(X[B,768] @ B1h^T + b1eff)
// 256 thr, tile 128x128, warp tile 64x32, K-chunk 64, double-buffered, occ 2
// ============================================================================
__global__ void __launch_bounds__(256, 2)
gemm1(const float* __restrict__ gE, const float* __restrict__ dE,
      const float* __restrict__ cE) {
    extern __shared__ char smem[];
    const uint32_t sb = smem_u32(smem);
    const int tid = threadIdx.x;
    const int wid = tid >> 5, lane = tid & 31;
    const int m0 = blockIdx.y * 128;
    const int n0 = blockIdx.x * 128;
    const int wm = (wid >> 2) * 64;
    const int wn = (wid & 3) * 32;
    const float* srcs[3] = {gE, dE, cE};

    float acc[4][4][4];
#pragma unroll
    for (int i = 0; i < 4; i++)
#pragma unroll
        for (int j = 0; j < 4; j++)
#pragma unroll
            for (int v = 0; v < 4; v++) acc[i][j][v] = 0.f;

    const int a_row[8] = { (0*256+tid) >> 4, (1*256+tid) >> 4, (2*256+tid) >> 4, (3*256+tid) >> 4,
                           (4*256+tid) >> 4, (5*256+tid) >> 4, (6*256+tid) >> 4, (7*256+tid) >> 4 };
    const int a_c4 = tid & 15;

    uint2 ah[8];   // A fragment converted to fp16 at load time

    // prologue: buffer 0 (kc = 0)
    {
        const float* src = srcs[0] + (size_t)m0 * 256;
#pragma unroll
        for (int i = 0; i < 8; i++) {
            float4 f = *(const float4*)(src + (size_t)a_row[i] * 256 + a_c4 * 4);
            __half2 h0 = __floats2half2_rn(f.x, f.y);
            __half2 h1 = __floats2half2_rn(f.z, f.w);
            ah[i].x = *(uint32_t*)&h0;
            ah[i].y = *(uint32_t*)&h1;
        }
#pragma unroll
        for (int i = 0; i < 8; i++)
            *(uint2*)(smem + SM_A0 + swz(a_row[i], a_c4 * 4)) = ah[i];
#pragma unroll
        for (int i = 0; i < 4; i++) {
            int idx = i * 256 + tid;
            int row = idx >> 3, c = idx & 7;
            cp_async16(sb + SM_B0 + swz(row, c * 8), g_B1h + (size_t)(n0 + row) * KIN + c * 8);
        }
        cp_commit();
        cp_wait0();
        __syncthreads();
    }

    const int NITER = 12;
    for (int kc = 0; kc < NITER; kc++) {
        const uint32_t Abase = sb + (kc & 1 ? SM_A1 : SM_A0);
        const uint32_t Bbase = sb + (kc & 1 ? SM_B1 : SM_B0);
        const int nxt = kc + 1;
        const uint32_t AbaseN = sb + (nxt & 1 ? SM_A1 : SM_A0);
        const uint32_t BbaseN = sb + (nxt & 1 ? SM_B1 : SM_B0);

        if (nxt < NITER) {
            const float* src = srcs[nxt >> 2] + (size_t)m0 * 256 + (nxt & 3) * 64;
#pragma unroll
            for (int i = 0; i < 8; i++) {
                float4 f = *(const float4*)(src + (size_t)a_row[i] * 256 + a_c4 * 4);
                __half2 h0 = __floats2half2_rn(f.x, f.y);
                __half2 h1 = __floats2half2_rn(f.z, f.w);
                ah[i].x = *(uint32_t*)&h0;
                ah[i].y = *(uint32_t*)&h1;
            }
#pragma unroll
            for (int i = 0; i < 4; i++) {
                int idx = i * 256 + tid;
                int row = idx >> 3, c = idx & 7;
                cp_async16(BbaseN + swz(row, c * 8),
                           g_B1h + (size_t)(n0 + row) * KIN + nxt * 64 + c * 8);
            }
            cp_commit();
        }

        // compute on current buffers
#pragma unroll
        for (int ks = 0; ks < 64; ks += 16) {
            uint32_t a[4][4], b[8];
#pragma unroll
            for (int t = 0; t < 4; t++) {
                uint32_t row = wm + t * 16 + (lane & 15);
                uint32_t kk  = ks + (lane >> 4) * 8;
                ldm_x4(a[t][0], a[t][1], a[t][2], a[t][3], Abase + swz(row, kk));
            }
#pragma unroll
            for (int h = 0; h < 2; h++) {
                int g = lane >> 3, ri = lane & 7;
                uint32_t nrow = wn + h * 16 + (g >> 1) * 8 + ri;
                uint32_t kk   = ks + (g & 1) * 8;
                ldm_x4(b[h * 4 + 0], b[h * 4 + 1], b[h * 4 + 2], b[h * 4 + 3],
                       Bbase + swz(nrow, kk));
            }
#pragma unroll
            for (int mt = 0; mt < 4; mt++)
#pragma unroll
                for (int nt = 0; nt < 4; nt++)
                    mma16816(acc[mt][nt], a[mt][0], a[mt][1], a[mt][2], a[mt][3],
                             b[nt * 2], b[nt * 2 + 1]);
        }

        if (nxt < NITER) {
#pragma unroll
            for (int i = 0; i < 8; i++)
                *(uint2*)((char*)smem + (AbaseN - sb) + swz(a_row[i], a_c4 * 4)) = ah[i];
            cp_wait0();
        }
        __syncthreads();
    }

    // epilogue: relu(acc + b1eff) -> fp16 g_H
#pragma unroll
    for (int mt = 0; mt < 4; mt++) {
#pragma unroll
        for (int nt = 0; nt < 4; nt++) {
            int n = n0 + wn + nt * 8 + (lane & 3) * 2;
            float bia0 = g_b1eff[n], bia1 = g_b1eff[n + 1];
            int r0 = m0 + wm + mt * 16 + (lane >> 2);
            float v0 = fmaxf(acc[mt][nt][0] + bia0, 0.f);
            float v1 = fmaxf(acc[mt][nt][1] + bia1, 0.f);
            float v2 = fmaxf(acc[mt][nt][2] + bia0, 0.f);
            float v3 = fmaxf(acc[mt][nt][3] + bia1, 0.f);
            __half2 h01 = __floats2half2_rn(v0, v1);
            __half2 h23 = __floats2half2_rn(v2, v3);
            *(__half2*)(g_H + (size_t)r0 * HIDN + n)       = h01;
            *(__half2*)(g_H + (size_t)(r0 + 8) * HIDN + n) = h23;
        }
    }
}

// ============================================================================
// GEMM2 (R6 winner): out[B,256] = g_H[B,512] @ W2h^T + b2, fp32 out, occ 2
// ============================================================================
__global__ void __launch_bounds__(256, 2)
gemm2(const float* __restrict__ b2, float* __restrict__ out) {
    extern __shared__ char smem[];
    const uint32_t sb = smem_u32(smem);
    const int tid = threadIdx.x;
    const int wid = tid >> 5, lane = tid & 31;
    const int m0 = blockIdx.y * 128;
    const int n0 = blockIdx.x * 128;
    const int wm = (wid >> 2) * 64;
    const int wn = (wid & 3) * 32;

    float acc[4][4][4];
#pragma unroll
    for (int i = 0; i < 4; i++)
#pragma unroll
        for (int j = 0; j < 4; j++)
#pragma unroll
            for (int v = 0; v < 4; v++) acc[i][j][v] = 0.f;

    // prologue buffer 0
    {
#pragma unroll
        for (int i = 0; i < 4; i++) {
            int idx = i * 256 + tid;
            int row = idx >> 3, c = idx & 7;
            cp_async16(sb + SM_A0 + swz(row, c * 8), g_H + (size_t)(m0 + row) * HIDN + c * 8);
            cp_async16(sb + SM_B0 + swz(row, c * 8), g_W2h + (size_t)(n0 + row) * HIDN + c * 8);
        }
        cp_commit();
        cp_wait0();
        __syncthreads();
    }

    const int NITER = 8;
    for (int kc = 0; kc < NITER; kc++) {
        const uint32_t Abase = sb + (kc & 1 ? SM_A1 : SM_A0);
        const uint32_t Bbase = sb + (kc & 1 ? SM_B1 : SM_B0);
        const int nxt = kc + 1;

        if (nxt < NITER) {
            uint32_t AbaseN = sb + (nxt & 1 ? SM_A1 : SM_A0);
            uint32_t BbaseN = sb + (nxt & 1 ? SM_B1 : SM_B0);
#pragma unroll
            for (int i = 0; i < 4; i++) {
                int idx = i * 256 + tid;
                int row = idx >> 3, c = idx & 7;
                cp_async16(AbaseN + swz(row, c * 8),
                           g_H + (size_t)(m0 + row) * HIDN + nxt * 64 + c * 8);
                cp_async16(BbaseN + swz(row, c * 8),
                           g_W2h + (size_t)(n0 + row) * HIDN + nxt * 64 + c * 8);
            }
            cp_commit();
        }

#pragma unroll
        for (int ks = 0; ks < 64; ks += 16) {
            uint32_t a[4][4], b[8];
#pragma unroll
            for (int t = 0; t < 4; t++) {
                uint32_t row = wm + t * 16 + (lane & 15);
                uint32_t kk  = ks + (lane >> 4) * 8;
                ldm_x4(a[t][0], a[t][1], a[t][2], a[t][3], Abase + swz(row, kk));
            }
#pragma unroll
            for (int h = 0; h < 2; h++) {
                int g = lane >> 3, ri = lane & 7;
                uint32_t nrow = wn + h * 16 + (g >> 1) * 8 + ri;
                uint32_t kk   = ks + (g & 1) * 8;
                ldm_x4(b[h * 4 + 0], b[h * 4 + 1], b[h * 4 + 2], b[h * 4 + 3],
                       Bbase + swz(nrow, kk));
            }
#pragma unroll
            for (int mt = 0; mt < 4; mt++)
#pragma unroll
                for (int nt = 0; nt < 4; nt++)
                    mma16816(acc[mt][nt], a[mt][0], a[mt][1], a[mt][2], a[mt][3],
                             b[nt * 2], b[nt * 2 + 1]);
        }

        if (nxt < NITER) cp_wait0();
        __syncthreads();
    }

    // epilogue: acc + b2 -> fp32 out
#pragma unroll
    for (int mt = 0; mt < 4; mt++) {
#pragma unroll
        for (int nt = 0; nt < 4; nt++) {
            int n = n0 + wn + nt * 8 + (lane & 3) * 2;
            float bia0 = b2[n], bia1 = b2[n + 1];
            int r0 = m0 + wm + mt * 16 + (lane >> 2);
            float2 o01 = { acc[mt][nt][0] + bia0, acc[mt][nt][1] + bia1 };
            float2 o23 = { acc[mt][nt][2] + bia0, acc[mt][nt][3] + bia1 };
            *(float2*)(out + (size_t)r0 * EDIM + n)       = o01;
            *(float2*)(out + (size_t)(r0 + 8) * EDIM + n) = o23;
        }
    }
}

// ============================================================================
// kernel_launch
// Input order: g, d, c, Wq, Wk, Wv, bq, bk, bv, Wo, bo, W1, b1, W2, b2
// ============================================================================
extern "C" void kernel_launch(void* const* d_in, const int* in_sizes, int n_in,
                              void* d_out, int out_size) {
    const float* g  = (const float*)d_in[0];
    const float* dd = (const float*)d_in[1];
    const float* cc = (const float*)d_in[2];
    const float* Wv = (const float*)d_in[5];
    const float* bv = (const float*)d_in[8];
    const float* Wo = (const float*)d_in[9];
    const float* bo = (const float*)d_in[10];
    const float* W1 = (const float*)d_in[11];
    const float* b1 = (const float*)d_in[12];
    const float* W2 = (const float*)d_in[13];
    const float* b2 = (const float*)d_in[14];
    const int B = in_sizes[0] / EDIM;

    cudaFuncSetAttribute(k_Mmma,  cudaFuncAttributeMaxDynamicSharedMemorySize, SMEM_G);
    cudaFuncSetAttribute(k_B1mma, cudaFuncAttributeMaxDynamicSharedMemorySize, SMEM_G);
    cudaFuncSetAttribute(gemm1,   cudaFuncAttributeMaxDynamicSharedMemorySize, SMEM_G);
    cudaFuncSetAttribute(gemm2,   cudaFuncAttributeMaxDynamicSharedMemorySize, SMEM_G);

    // Precompute chain — all GEMMs on tensor cores now:
    k_cvec  <<<6, 256>>>(Wo, bv, bo);
    k_h16   <<<3584, 256>>>(W1, W2, Wo);           // W1h, W2h, Woh
    k_wt    <<<dim3(8, 8, 6), dim3(32, 8)>>>(Wv);  // Wv -> Wvt fp16 (transposed)
    k_Mmma  <<<dim3(2, 2, 6), 256, SMEM_G>>>();    // M via mma -> g_Bc directly
    k_B1mma <<<dim3(2, 4, 3), 256, SMEM_G>>>(W1);  // tensor-core fold (+W1, ->fp16)
    k_b1eff <<<HIDN, 256>>>(W1, b1);

    gemm1<<<dim3(4, B / 128), 256, SMEM_G>>>(g, dd, cc);
    gemm2<<<dim3(2, B / 128), 256, SMEM_G>>>(b2, (float*)d_out);
}

// round 13
// speedup vs baseline: 1.0673x; 1.0210x over previous
#include <cuda_runtime.h>
#include <cuda_fp16.h>
#include <cstdint>

// ============================================================================
// Problem constants
// ============================================================================
#define EDIM 256      // E
#define HIDN 512      // 2E
#define KIN  768      // 3E
#define BTOT 131072

// ============================================================================
// Device scratch (allocation-free rule: __device__ globals)
// ============================================================================
__device__ float  g_cvec[6 * EDIM];                      // c_i = Wo_i @ bv_i + bo_i
__device__ float  g_b1eff[HIDN];                         // b1 + Kvec @ W1^T
__device__ __align__(16) __half g_W1h[HIDN * KIN];       // W1 fp16
__device__ __align__(16) __half g_Woh[6 * EDIM * EDIM];  // Wo fp16 [i][e][m]
__device__ __align__(16) __half g_Wvt[6 * EDIM * EDIM];  // Wv fp16 transposed [i][kp][m]
__device__ __align__(16) __half g_Bc[3 * EDIM * HIDN];   // repacked M: [r][kp][qe] fp16
__device__ __align__(16) __half g_B1h[HIDN * KIN];       // folded W1, fp16 [N=512][K=768]
__device__ __align__(16) __half g_W2h[EDIM * HIDN];      // W2 fp16 [N=256][K=512]
__device__ __align__(16) __half g_H[(size_t)BTOT * HIDN];// hidden fp16 [131072][512]

// ============================================================================
// PTX helpers (baseline sm_80+ features only: mma.sync / ldmatrix / cp.async)
// ============================================================================
__device__ __forceinline__ uint32_t smem_u32(const void* p) {
    uint32_t a;
    asm("{ .reg .u64 t; cvta.to.shared.u64 t, %1; cvt.u32.u64 %0, t; }" : "=r"(a) : "l"(p));
    return a;
}

__device__ __forceinline__ void cp_async16(uint32_t saddr, const void* gaddr) {
    asm volatile("cp.async.cg.shared.global [%0], [%1], 16;" :: "r"(saddr), "l"(gaddr));
}
__device__ __forceinline__ void cp_commit() { asm volatile("cp.async.commit_group;" ::: "memory"); }
__device__ __forceinline__ void cp_wait0()  { asm volatile("cp.async.wait_group 0;" ::: "memory"); }

__device__ __forceinline__ void ldm_x4(uint32_t& r0, uint32_t& r1, uint32_t& r2, uint32_t& r3,
                                       uint32_t addr) {
    asm volatile("ldmatrix.sync.aligned.m8n8.x4.shared.b16 {%0,%1,%2,%3}, [%4];"
                 : "=r"(r0), "=r"(r1), "=r"(r2), "=r"(r3) : "r"(addr));
}

__device__ __forceinline__ void mma16816(float* c, uint32_t a0, uint32_t a1, uint32_t a2,
                                         uint32_t a3, uint32_t b0, uint32_t b1) {
    asm volatile(
        "mma.sync.aligned.m16n8k16.row.col.f32.f16.f16.f32 "
        "{%0,%1,%2,%3}, {%4,%5,%6,%7}, {%8,%9}, {%0,%1,%2,%3};"
        : "+f"(c[0]), "+f"(c[1]), "+f"(c[2]), "+f"(c[3])
        : "r"(a0), "r"(a1), "r"(a2), "r"(a3), "r"(b0), "r"(b1));
}

// XOR swizzle for [rows][64 halves] tiles (128B rows, 16B units, 8-way)
__device__ __forceinline__ uint32_t swz(uint32_t row, uint32_t k) {
    return row * 128u + ((((k >> 3) ^ (row & 7)) << 4) | ((k & 7) * 2u));
}

// ============================================================================
// k_prep: merged W1/W2/Wo->fp16, Wv transpose->fp16, cvec. grid 3974 x 256
//   [0,1536)    W1h      [1536,2048) W2h     [2048,3584) Woh
//   [3584,3968) Wv transpose tiles   [3968,3974) cvec
// ============================================================================
__global__ void __launch_bounds__(256) k_prep(const float* __restrict__ W1,
                                              const float* __restrict__ W2,
                                              const float* __restrict__ Wo,
                                              const float* __restrict__ Wv,
                                              const float* __restrict__ bv,
                                              const float* __restrict__ bo) {
    __shared__ float t[32][33];
    const int bi = blockIdx.x;
    const int tid = threadIdx.x;
    if (bi < 1536) {
        int idx = bi * 256 + tid;
        g_W1h[idx] = __float2half_rn(W1[idx]);
    } else if (bi < 2048) {
        int idx = (bi - 1536) * 256 + tid;
        g_W2h[idx] = __float2half_rn(W2[idx]);
    } else if (bi < 3584) {
        int idx = (bi - 2048) * 256 + tid;
        g_Woh[idx] = __float2half_rn(Wo[idx]);
    } else if (bi < 3968) {
        int idx = bi - 3584;
        int i = idx >> 6;
        int rem = idx & 63;
        int m0 = (rem & 7) * 32, kp0 = (rem >> 3) * 32;
        int tx = tid & 31, ty = tid >> 5;
        const float* src = Wv + i * 65536;
#pragma unroll
        for (int j = 0; j < 4; j++) {
            int row = ty + j * 8;
            t[row][tx] = src[(m0 + row) * 256 + kp0 + tx];
        }
        __syncthreads();
#pragma unroll
        for (int j = 0; j < 4; j++) {
            int row = ty + j * 8;   // kp-local
            g_Wvt[i * 65536 + (kp0 + row) * 256 + m0 + tx] = __float2half_rn(t[tx][row]);
        }
    } else {
        int i = bi - 3968, e = tid;
        const float* w = Wo + i * 65536 + e * 256;
        const float* b = bv + i * 256;
        float a0 = 0.f, a1 = 0.f, a2 = 0.f, a3 = 0.f;
#pragma unroll 4
        for (int m = 0; m < 256; m += 4) {
            a0 += w[m + 0] * b[m + 0];
            a1 += w[m + 1] * b[m + 1];
            a2 += w[m + 2] * b[m + 2];
            a3 += w[m + 3] * b[m + 3];
        }
        g_cvec[i * 256 + e] = bo[i * 256 + e] + (a0 + a1) + (a2 + a3);
    }
}

// b1eff[n] = b1[n] + sum_j csum[j] * W1[n][j]
__global__ void __launch_bounds__(256) k_b1eff(const float* __restrict__ W1,
                                               const float* __restrict__ b1) {
    const int n = blockIdx.x;
    const int tid = threadIdx.x;
    float p = 0.f;
#pragma unroll
    for (int jj = 0; jj < 3; jj++) {
        int j = jj * 256 + tid;
        int q = j >> 8, e = j & 255;
        float cs = g_cvec[(2 * q) * 256 + e] + g_cvec[(2 * q + 1) * 256 + e];
        p += cs * W1[n * KIN + j];
    }
    __shared__ float red[256];
    red[tid] = p;
    __syncthreads();
#pragma unroll
    for (int s = 128; s > 0; s >>= 1) {
        if (tid < s) red[tid] += red[tid + s];
        __syncthreads();
    }
    if (tid == 0) g_b1eff[n] = b1[n] + red[0];
}

// ============================================================================
// SMEM layouts
// ============================================================================
#define SM_A0 0
#define SM_A1 16384
#define SM_B0 32768
#define SM_B1 49152
#define SMEM_G 65536
// small-tile (64x64) mma kernels
#define SMM_A0 0
#define SMM_A1 8192
#define SMM_B0 16384
#define SMM_B1 24576
#define SMEM_M 32768

// ============================================================================
// k_Mmma: M_i[e][kp] = Woh_i[e][:] @ Wvt_i[kp][:]  (64x64 tiles, K=256)
// grid (4 kp, 4 e, 6 i), 128 thr / 4 warps (32x32 warp tile)
// epilogue writes g_Bc[r][kp][qi*256+e] fp16
// ============================================================================
__global__ void __launch_bounds__(128)
k_Mmma() {
    extern __shared__ char smem[];
    const uint32_t sb = smem_u32(smem);
    const int tid = threadIdx.x;
    const int wid = tid >> 5, lane = tid & 31;
    const int i   = blockIdx.z;
    const int e0c  = blockIdx.y * 64;
    const int kp0c = blockIdx.x * 64;
    const int wm = (wid >> 1) * 32;
    const int wn = (wid & 1) * 32;
    // i -> (r, qi): midx 0->(1,0) 1->(2,0) 2->(0,0) 3->(2,1) 4->(0,1) 5->(1,1)
    const int r  = (i == 0) ? 1 : (i == 1) ? 2 : (i == 2) ? 0 : (i == 3) ? 2 : (i == 4) ? 0 : 1;
    const int qi = (i <= 2) ? 0 : 1;
    const __half* Asrc = g_Woh + i * 65536;
    const __half* Bsrc = g_Wvt + i * 65536;

    float acc[2][4][4];
#pragma unroll
    for (int a = 0; a < 2; a++)
#pragma unroll
        for (int j = 0; j < 4; j++)
#pragma unroll
            for (int v = 0; v < 4; v++) acc[a][j][v] = 0.f;

    // prologue buffer 0 (4 x 16B per thread per operand)
    {
#pragma unroll
        for (int a = 0; a < 4; a++) {
            int idx = a * 128 + tid;
            int row = idx >> 3, c = idx & 7;
            cp_async16(sb + SMM_A0 + swz(row, c * 8), Asrc + (size_t)(e0c + row) * 256 + c * 8);
            cp_async16(sb + SMM_B0 + swz(row, c * 8), Bsrc + (size_t)(kp0c + row) * 256 + c * 8);
        }
        cp_commit();
        cp_wait0();
        __syncthreads();
    }

    const int NITER = 4;
    for (int kc = 0; kc < NITER; kc++) {
        const uint32_t Abase = sb + (kc & 1 ? SMM_A1 : SMM_A0);
        const uint32_t Bbase = sb + (kc & 1 ? SMM_B1 : SMM_B0);
        const int nxt = kc + 1;

        if (nxt < NITER) {
            uint32_t AbaseN = sb + (nxt & 1 ? SMM_A1 : SMM_A0);
            uint32_t BbaseN = sb + (nxt & 1 ? SMM_B1 : SMM_B0);
#pragma unroll
            for (int a = 0; a < 4; a++) {
                int idx = a * 128 + tid;
                int row = idx >> 3, c = idx & 7;
                cp_async16(AbaseN + swz(row, c * 8),
                           Asrc + (size_t)(e0c + row) * 256 + nxt * 64 + c * 8);
                cp_async16(BbaseN + swz(row, c * 8),
                           Bsrc + (size_t)(kp0c + row) * 256 + nxt * 64 + c * 8);
            }
            cp_commit();
        }

#pragma unroll
        for (int ks = 0; ks < 64; ks += 16) {
            uint32_t a[2][4], b[8];
#pragma unroll
            for (int t = 0; t < 2; t++) {
                uint32_t row = wm + t * 16 + (lane & 15);
                uint32_t kk  = ks + (lane >> 4) * 8;
                ldm_x4(a[t][0], a[t][1], a[t][2], a[t][3], Abase + swz(row, kk));
            }
#pragma unroll
            for (int h = 0; h < 2; h++) {
                int g = lane >> 3, ri = lane & 7;
                uint32_t nrow = wn + h * 16 + (g >> 1) * 8 + ri;
                uint32_t kk   = ks + (g & 1) * 8;
                ldm_x4(b[h * 4 + 0], b[h * 4 + 1], b[h * 4 + 2], b[h * 4 + 3],
                       Bbase + swz(nrow, kk));
            }
#pragma unroll
            for (int mt = 0; mt < 2; mt++)
#pragma unroll
                for (int nt = 0; nt < 4; nt++)
                    mma16816(acc[mt][nt], a[mt][0], a[mt][1], a[mt][2], a[mt][3],
                             b[nt * 2], b[nt * 2 + 1]);
        }

        if (nxt < NITER) cp_wait0();
        __syncthreads();
    }

    // epilogue: g_Bc[r][kp][qi*256 + e] = fp16(M[e][kp])
    __half* dst = g_Bc + r * 131072 + qi * 256;
#pragma unroll
    for (int mt = 0; mt < 2; mt++) {
#pragma unroll
        for (int nt = 0; nt < 4; nt++) {
            int kp = kp0c + wn + nt * 8 + (lane & 3) * 2;
            int e  = e0c + wm + mt * 16 + (lane >> 2);
            dst[(size_t)kp * 512 + e]           = __float2half_rn(acc[mt][nt][0]);
            dst[(size_t)(kp + 1) * 512 + e]     = __float2half_rn(acc[mt][nt][1]);
            dst[(size_t)kp * 512 + e + 8]       = __float2half_rn(acc[mt][nt][2]);
            dst[(size_t)(kp + 1) * 512 + e + 8] = __float2half_rn(acc[mt][nt][3]);
        }
    }
}

// ============================================================================
// k_B1mma: per r, fold[n][kp] = W1h[n, qe-sel] @ Bc[r]^T + W1 (64x64 tiles)
// grid (4 kp-chunks, 8 n-chunks, 3 r), 128 thr; K=512 (two q blocks of 256)
// ============================================================================
__global__ void __launch_bounds__(128)
k_B1mma(const float* __restrict__ W1) {
    extern __shared__ char smem[];
    const uint32_t sb = smem_u32(smem);
    const int tid = threadIdx.x;
    const int wid = tid >> 5, lane = tid & 31;
    const int m0 = blockIdx.y * 64;         // n-dim (rows of W1)
    const int n0 = blockIdx.x * 64;         // kp-dim
    const int r  = blockIdx.z;
    const int wm = (wid >> 1) * 32;
    const int wn = (wid & 1) * 32;
    const int q0 = (r == 0) ? 1 : 0;
    const int q1 = (r == 2) ? 1 : 2;
    const __half* Bsrc = g_Bc + r * 131072;

    float acc[2][4][4];
#pragma unroll
    for (int i = 0; i < 2; i++)
#pragma unroll
        for (int j = 0; j < 4; j++)
#pragma unroll
            for (int v = 0; v < 4; v++) acc[i][j][v] = 0.f;

    // prologue: buffer 0 (kc = 0 -> q = q0, colpart 0)
    {
#pragma unroll
        for (int i = 0; i < 4; i++) {
            int idx = i * 128 + tid;
            int row = idx >> 3, c = idx & 7;
            cp_async16(sb + SMM_A0 + swz(row, c * 8),
                       g_W1h + (size_t)(m0 + row) * KIN + q0 * 256 + c * 8);
            cp_async16(sb + SMM_B0 + swz(row, c * 8),
                       Bsrc + (size_t)(n0 + row) * 512 + c * 8);
        }
        cp_commit();
        cp_wait0();
        __syncthreads();
    }

    const int NITER = 8;
    for (int kc = 0; kc < NITER; kc++) {
        const uint32_t Abase = sb + (kc & 1 ? SMM_A1 : SMM_A0);
        const uint32_t Bbase = sb + (kc & 1 ? SMM_B1 : SMM_B0);
        const int nxt = kc + 1;

        if (nxt < NITER) {
            uint32_t AbaseN = sb + (nxt & 1 ? SMM_A1 : SMM_A0);
            uint32_t BbaseN = sb + (nxt & 1 ? SMM_B1 : SMM_B0);
            int q = (nxt >> 2) ? q1 : q0;
            int colbase = q * 256 + (nxt & 3) * 64;
#pragma unroll
            for (int i = 0; i < 4; i++) {
                int idx = i * 128 + tid;
                int row = idx >> 3, c = idx & 7;
                cp_async16(AbaseN + swz(row, c * 8),
                           g_W1h + (size_t)(m0 + row) * KIN + colbase + c * 8);
                cp_async16(BbaseN + swz(row, c * 8),
                           Bsrc + (size_t)(n0 + row) * 512 + nxt * 64 + c * 8);
            }
            cp_commit();
        }

#pragma unroll
        for (int ks = 0; ks < 64; ks += 16) {
            uint32_t a[2][4], b[8];
#pragma unroll
            for (int t = 0; t < 2; t++) {
                uint32_t row = wm + t * 16 + (lane & 15);
                uint32_t kk  = ks + (lane >> 4) * 8;
                ldm_x4(a[t][0], a[t][1], a[t][2], a[t][3], Abase + swz(row, kk));
            }
#pragma unroll
            for (int h = 0; h < 2; h++) {
                int g = lane >> 3, ri = lane & 7;
                uint32_t nrow = wn + h * 16 + (g >> 1) * 8 + ri;
                uint32_t kk   = ks + (g & 1) * 8;
                ldm_x4(b[h * 4 + 0], b[h * 4 + 1], b[h * 4 + 2], b[h * 4 + 3],
                       Bbase + swz(nrow, kk));
            }
#pragma unroll
            for (int mt = 0; mt < 2; mt++)
#pragma unroll
                for (int nt = 0; nt < 4; nt++)
                    mma16816(acc[mt][nt], a[mt][0], a[mt][1], a[mt][2], a[mt][3],
                             b[nt * 2], b[nt * 2 + 1]);
        }

        if (nxt < NITER) cp_wait0();
        __syncthreads();
    }

    // epilogue: B1h[n][r*256+kp] = fp16(W1[n][r*256+kp] + acc)
#pragma unroll
    for (int mt = 0; mt < 2; mt++) {
#pragma unroll
        for (int nt = 0; nt < 4; nt++) {
            int kp = n0 + wn + nt * 8 + (lane & 3) * 2;
            int nrow0 = m0 + wm + mt * 16 + (lane >> 2);
            size_t base0 = (size_t)nrow0 * KIN + r * 256 + kp;
            size_t base1 = (size_t)(nrow0 + 8) * KIN + r * 256 + kp;
            __half2 h01 = __floats2half2_rn(W1[base0] + acc[mt][nt][0],
                                            W1[base0 + 1] + acc[mt][nt][1]);
            __half2 h23 = __floats2half2_rn(W1[base1] + acc[mt][nt][2],
                                            W1[base1 + 1] + acc[mt][nt][3]);
            *(__half2*)(g_B1h + base0) = h01;
            *(__half2*)(g_B1h + base1) = h23;
        }
    }
}

// ============================================================================
// GEMM1 (R6 winner): hidden[B,512] = relu(X[B,768] @ B1h^T + b1eff)
// 256 thr, tile 128x128, warp tile 64x32, K-chunk 64, double-buffered, occ 2
// ============================================================================
__global__ void __launch_bounds__(256, 2)
gemm1(const float* __restrict__ gE, const float* __restrict__ dE,
      const float* __restrict__ cE) {
    extern __shared__ char smem[];
    const uint32_t sb = smem_u32(smem);
    const int tid = threadIdx.x;
    const int wid = tid >> 5, lane = tid & 31;
    const int m0 = blockIdx.y * 128;
    const int n0 = blockIdx.x * 128;
    const int wm = (wid >> 2) * 64;
    const int wn = (wid & 3) * 32;
    const float* srcs[3] = {gE, dE, cE};

    float acc[4][4][4];
#pragma unroll
    for (int i = 0; i < 4; i++)
#pragma unroll
        for (int j = 0; j < 4; j++)
#pragma unroll
            for (int v = 0; v < 4; v++) acc[i][j][v] = 0.f;

    const int a_row[8] = { (0*256+tid) >> 4, (1*256+tid) >> 4, (2*256+tid) >> 4, (3*256+tid) >> 4,
                           (4*256+tid) >> 4, (5*256+tid) >> 4, (6*256+tid) >> 4, (7*256+tid) >> 4 };
    const int a_c4 = tid & 15;

    uint2 ah[8];   // A fragment converted to fp16 at load time

    // prologue: buffer 0 (kc = 0)
    {
        const float* src = srcs[0] + (size_t)m0 * 256;
#pragma unroll
        for (int i = 0; i < 8; i++) {
            float4 f = *(const float4*)(src + (size_t)a_row[i] * 256 + a_c4 * 4);
            __half2 h0 = __floats2half2_rn(f.x, f.y);
            __half2 h1 = __floats2half2_rn(f.z, f.w);
            ah[i].x = *(uint32_t*)&h0;
            ah[i].y = *(uint32_t*)&h1;
        }
#pragma unroll
        for (int i = 0; i < 8; i++)
            *(uint2*)(smem + SM_A0 + swz(a_row[i], a_c4 * 4)) = ah[i];
#pragma unroll
        for (int i = 0; i < 4; i++) {
            int idx = i * 256 + tid;
            int row = idx >> 3, c = idx & 7;
            cp_async16(sb + SM_B0 + swz(row, c * 8), g_B1h + (size_t)(n0 + row) * KIN + c * 8);
        }
        cp_commit();
        cp_wait0();
        __syncthreads();
    }

    const int NITER = 12;
    for (int kc = 0; kc < NITER; kc++) {
        const uint32_t Abase = sb + (kc & 1 ? SM_A1 : SM_A0);
        const uint32_t Bbase = sb + (kc & 1 ? SM_B1 : SM_B0);
        const int nxt = kc + 1;
        const uint32_t AbaseN = sb + (nxt & 1 ? SM_A1 : SM_A0);
        const uint32_t BbaseN = sb + (nxt & 1 ? SM_B1 : SM_B0);

        if (nxt < NITER) {
            const float* src = srcs[nxt >> 2] + (size_t)m0 * 256 + (nxt & 3) * 64;
#pragma unroll
            for (int i = 0; i < 8; i++) {
                float4 f = *(const float4*)(src + (size_t)a_row[i] * 256 + a_c4 * 4);
                __half2 h0 = __floats2half2_rn(f.x, f.y);
                __half2 h1 = __floats2half2_rn(f.z, f.w);
                ah[i].x = *(uint32_t*)&h0;
                ah[i].y = *(uint32_t*)&h1;
            }
#pragma unroll
            for (int i = 0; i < 4; i++) {
                int idx = i * 256 + tid;
                int row = idx >> 3, c = idx & 7;
                cp_async16(BbaseN + swz(row, c * 8),
                           g_B1h + (size_t)(n0 + row) * KIN + nxt * 64 + c * 8);
            }
            cp_commit();
        }

        // compute on current buffers
#pragma unroll
        for (int ks = 0; ks < 64; ks += 16) {
            uint32_t a[4][4], b[8];
#pragma unroll
            for (int t = 0; t < 4; t++) {
                uint32_t row = wm + t * 16 + (lane & 15);
                uint32_t kk  = ks + (lane >> 4) * 8;
                ldm_x4(a[t][0], a[t][1], a[t][2], a[t][3], Abase + swz(row, kk));
            }
#pragma unroll
            for (int h = 0; h < 2; h++) {
                int g = lane >> 3, ri = lane & 7;
                uint32_t nrow = wn + h * 16 + (g >> 1) * 8 + ri;
                uint32_t kk   = ks + (g & 1) * 8;
                ldm_x4(b[h * 4 + 0], b[h * 4 + 1], b[h * 4 + 2], b[h * 4 + 3],
                       Bbase + swz(nrow, kk));
            }
#pragma unroll
            for (int mt = 0; mt < 4; mt++)
#pragma unroll
                for (int nt = 0; nt < 4; nt++)
                    mma16816(acc[mt][nt], a[mt][0], a[mt][1], a[mt][2], a[mt][3],
                             b[nt * 2], b[nt * 2 + 1]);
        }

        if (nxt < NITER) {
#pragma unroll
            for (int i = 0; i < 8; i++)
                *(uint2*)((char*)smem + (AbaseN - sb) + swz(a_row[i], a_c4 * 4)) = ah[i];
            cp_wait0();
        }
        __syncthreads();
    }

    // epilogue: relu(acc + b1eff) -> fp16 g_H
#pragma unroll
    for (int mt = 0; mt < 4; mt++) {
#pragma unroll
        for (int nt = 0; nt < 4; nt++) {
            int n = n0 + wn + nt * 8 + (lane & 3) * 2;
            float bia0 = g_b1eff[n], bia1 = g_b1eff[n + 1];
            int r0 = m0 + wm + mt * 16 + (lane >> 2);
            float v0 = fmaxf(acc[mt][nt][0] + bia0, 0.f);
            float v1 = fmaxf(acc[mt][nt][1] + bia1, 0.f);
            float v2 = fmaxf(acc[mt][nt][2] + bia0, 0.f);
            float v3 = fmaxf(acc[mt][nt][3] + bia1, 0.f);
            __half2 h01 = __floats2half2_rn(v0, v1);
            __half2 h23 = __floats2half2_rn(v2, v3);
            *(__half2*)(g_H + (size_t)r0 * HIDN + n)       = h01;
            *(__half2*)(g_H + (size_t)(r0 + 8) * HIDN + n) = h23;
        }
    }
}

// ============================================================================
// GEMM2 (R6 winner): out[B,256] = g_H[B,512] @ W2h^T + b2, fp32 out, occ 2
// ============================================================================
__global__ void __launch_bounds__(256, 2)
gemm2(const float* __restrict__ b2, float* __restrict__ out) {
    extern __shared__ char smem[];
    const uint32_t sb = smem_u32(smem);
    const int tid = threadIdx.x;
    const int wid = tid >> 5, lane = tid & 31;
    const int m0 = blockIdx.y * 128;
    const int n0 = blockIdx.x * 128;
    const int wm = (wid >> 2) * 64;
    const int wn = (wid & 3) * 32;

    float acc[4][4][4];
#pragma unroll
    for (int i = 0; i < 4; i++)
#pragma unroll
        for (int j = 0; j < 4; j++)
#pragma unroll
            for (int v = 0; v < 4; v++) acc[i][j][v] = 0.f;

    // prologue buffer 0
    {
#pragma unroll
        for (int i = 0; i < 4; i++) {
            int idx = i * 256 + tid;
            int row = idx >> 3, c = idx & 7;
            cp_async16(sb + SM_A0 + swz(row, c * 8), g_H + (size_t)(m0 + row) * HIDN + c * 8);
            cp_async16(sb + SM_B0 + swz(row, c * 8), g_W2h + (size_t)(n0 + row) * HIDN + c * 8);
        }
        cp_commit();
        cp_wait0();
        __syncthreads();
    }

    const int NITER = 8;
    for (int kc = 0; kc < NITER; kc++) {
        const uint32_t Abase = sb + (kc & 1 ? SM_A1 : SM_A0);
        const uint32_t Bbase = sb + (kc & 1 ? SM_B1 : SM_B0);
        const int nxt = kc + 1;

        if (nxt < NITER) {
            uint32_t AbaseN = sb + (nxt & 1 ? SM_A1 : SM_A0);
            uint32_t BbaseN = sb + (nxt & 1 ? SM_B1 : SM_B0);
#pragma unroll
            for (int i = 0; i < 4; i++) {
                int idx = i * 256 + tid;
                int row = idx >> 3, c = idx & 7;
                cp_async16(AbaseN + swz(row, c * 8),
                           g_H + (size_t)(m0 + row) * HIDN + nxt * 64 + c * 8);
                cp_async16(BbaseN + swz(row, c * 8),
                           g_W2h + (size_t)(n0 + row) * HIDN + nxt * 64 + c * 8);
            }
            cp_commit();
        }

#pragma unroll
        for (int ks = 0; ks < 64; ks += 16) {
            uint32_t a[4][4], b[8];
#pragma unroll
            for (int t = 0; t < 4; t++) {
                uint32_t row = wm + t * 16 + (lane & 15);
                uint32_t kk  = ks + (lane >> 4) * 8;
                ldm_x4(a[t][0], a[t][1], a[t][2], a[t][3], Abase + swz(row, kk));
            }
#pragma unroll
            for (int h = 0; h < 2; h++) {
                int g = lane >> 3, ri = lane & 7;
                uint32_t nrow = wn + h * 16 + (g >> 1) * 8 + ri;
                uint32_t kk   = ks + (g & 1) * 8;
                ldm_x4(b[h * 4 + 0], b[h * 4 + 1], b[h * 4 + 2], b[h * 4 + 3],
                       Bbase + swz(nrow, kk));
            }
#pragma unroll
            for (int mt = 0; mt < 4; mt++)
#pragma unroll
                for (int nt = 0; nt < 4; nt++)
                    mma16816(acc[mt][nt], a[mt][0], a[mt][1], a[mt][2], a[mt][3],
                             b[nt * 2], b[nt * 2 + 1]);
        }

        if (nxt < NITER) cp_wait0();
        __syncthreads();
    }

    // epilogue: acc + b2 -> fp32 out
#pragma unroll
    for (int mt = 0; mt < 4; mt++) {
#pragma unroll
        for (int nt = 0; nt < 4; nt++) {
            int n = n0 + wn + nt * 8 + (lane & 3) * 2;
            float bia0 = b2[n], bia1 = b2[n + 1];
            int r0 = m0 + wm + mt * 16 + (lane >> 2);
            float2 o01 = { acc[mt][nt][0] + bia0, acc[mt][nt][1] + bia1 };
            float2 o23 = { acc[mt][nt][2] + bia0, acc[mt][nt][3] + bia1 };
            *(float2*)(out + (size_t)r0 * EDIM + n)       = o01;
            *(float2*)(out + (size_t)(r0 + 8) * EDIM + n) = o23;
        }
    }
}

// ============================================================================
// kernel_launch
// Input order: g, d, c, Wq, Wk, Wv, bq, bk, bv, Wo, bo, W1, b1, W2, b2
// ============================================================================
extern "C" void kernel_launch(void* const* d_in, const int* in_sizes, int n_in,
                              void* d_out, int out_size) {
    const float* g  = (const float*)d_in[0];
    const float* dd = (const float*)d_in[1];
    const float* cc = (const float*)d_in[2];
    const float* Wv = (const float*)d_in[5];
    const float* bv = (const float*)d_in[8];
    const float* Wo = (const float*)d_in[9];
    const float* bo = (const float*)d_in[10];
    const float* W1 = (const float*)d_in[11];
    const float* b1 = (const float*)d_in[12];
    const float* W2 = (const float*)d_in[13];
    const float* b2 = (const float*)d_in[14];
    const int B = in_sizes[0] / EDIM;

    cudaFuncSetAttribute(k_Mmma,  cudaFuncAttributeMaxDynamicSharedMemorySize, SMEM_M);
    cudaFuncSetAttribute(k_B1mma, cudaFuncAttributeMaxDynamicSharedMemorySize, SMEM_M);
    cudaFuncSetAttribute(gemm1,   cudaFuncAttributeMaxDynamicSharedMemorySize, SMEM_G);
    cudaFuncSetAttribute(gemm2,   cudaFuncAttributeMaxDynamicSharedMemorySize, SMEM_G);

    // Precompute chain: 4 launches (was 6)
    k_prep  <<<3974, 256>>>(W1, W2, Wo, Wv, bv, bo);         // fp16 conv + transpose + cvec
    k_Mmma  <<<dim3(4, 4, 6), 128, SMEM_M>>>();              // M via mma -> g_Bc (96 CTAs)
    k_B1mma <<<dim3(4, 8, 3), 128, SMEM_M>>>(W1);            // fold (+W1 -> fp16) (96 CTAs)
    k_b1eff <<<HIDN, 256>>>(W1, b1);

    gemm1<<<dim3(4, B / 128), 256, SMEM_G>>>(g, dd, cc);
    gemm2<<<dim3(2, B / 128), 256, SMEM_G>>>(b2, (float*)d_out);
}

// round 14
// speedup vs baseline: 1.0710x; 1.0035x over previous
#include <cuda_runtime.h>
#include <cuda_fp16.h>
#include <cstdint>

// ============================================================================
// Problem constants
// ============================================================================
#define EDIM 256      // E
#define HIDN 512      // 2E
#define KIN  768      // 3E
#define BTOT 131072

// ============================================================================
// Device scratch (allocation-free rule: __device__ globals)
// ============================================================================
__device__ float  g_cvec[6 * EDIM];                      // c_i = Wo_i @ bv_i + bo_i
__device__ float  g_b1eff[HIDN];                         // b1 + Kvec @ W1^T
__device__ __align__(16) __half g_W1h[HIDN * KIN];       // W1 fp16
__device__ __align__(16) __half g_Woh[6 * EDIM * EDIM];  // Wo fp16 [i][e][m]
__device__ __align__(16) __half g_Wvt[6 * EDIM * EDIM];  // Wv fp16 transposed [i][kp][m]
__device__ __align__(16) __half g_Bc[3 * EDIM * HIDN];   // repacked M: [r][kp][qe] fp16
__device__ __align__(16) __half g_B1h[HIDN * KIN];       // folded W1, fp16 [N=512][K=768]
__device__ __align__(16) __half g_W2h[EDIM * HIDN];      // W2 fp16 [N=256][K=512]
__device__ __align__(16) __half g_H[(size_t)BTOT * HIDN];// hidden fp16 [131072][512]

// ============================================================================
// PTX helpers (baseline sm_80+ features only: mma.sync / ldmatrix / cp.async)
// ============================================================================
__device__ __forceinline__ uint32_t smem_u32(const void* p) {
    uint32_t a;
    asm("{ .reg .u64 t; cvta.to.shared.u64 t, %1; cvt.u32.u64 %0, t; }" : "=r"(a) : "l"(p));
    return a;
}

__device__ __forceinline__ void cp_async16(uint32_t saddr, const void* gaddr) {
    asm volatile("cp.async.cg.shared.global [%0], [%1], 16;" :: "r"(saddr), "l"(gaddr));
}
__device__ __forceinline__ void cp_commit() { asm volatile("cp.async.commit_group;" ::: "memory"); }
__device__ __forceinline__ void cp_wait0()  { asm volatile("cp.async.wait_group 0;" ::: "memory"); }

__device__ __forceinline__ void ldm_x4(uint32_t& r0, uint32_t& r1, uint32_t& r2, uint32_t& r3,
                                       uint32_t addr) {
    asm volatile("ldmatrix.sync.aligned.m8n8.x4.shared.b16 {%0,%1,%2,%3}, [%4];"
                 : "=r"(r0), "=r"(r1), "=r"(r2), "=r"(r3) : "r"(addr));
}

__device__ __forceinline__ void mma16816(float* c, uint32_t a0, uint32_t a1, uint32_t a2,
                                         uint32_t a3, uint32_t b0, uint32_t b1) {
    asm volatile(
        "mma.sync.aligned.m16n8k16.row.col.f32.f16.f16.f32 "
        "{%0,%1,%2,%3}, {%4,%5,%6,%7}, {%8,%9}, {%0,%1,%2,%3};"
        : "+f"(c[0]), "+f"(c[1]), "+f"(c[2]), "+f"(c[3])
        : "r"(a0), "r"(a1), "r"(a2), "r"(a3), "r"(b0), "r"(b1));
}

// XOR swizzle for [rows][64 halves] tiles (128B rows, 16B units, 8-way)
__device__ __forceinline__ uint32_t swz(uint32_t row, uint32_t k) {
    return row * 128u + ((((k >> 3) ^ (row & 7)) << 4) | ((k & 7) * 2u));
}

// ============================================================================
// k_prep: merged W1/W2/Wo->fp16, Wv transpose->fp16, cvec. grid 3974 x 256
//   [0,1536)    W1h      [1536,2048) W2h     [2048,3584) Woh
//   [3584,3968) Wv transpose tiles   [3968,3974) cvec
// ============================================================================
__global__ void __launch_bounds__(256) k_prep(const float* __restrict__ W1,
                                              const float* __restrict__ W2,
                                              const float* __restrict__ Wo,
                                              const float* __restrict__ Wv,
                                              const float* __restrict__ bv,
                                              const float* __restrict__ bo) {
    __shared__ float t[32][33];
    const int bi = blockIdx.x;
    const int tid = threadIdx.x;
    if (bi < 1536) {
        int idx = bi * 256 + tid;
        g_W1h[idx] = __float2half_rn(W1[idx]);
    } else if (bi < 2048) {
        int idx = (bi - 1536) * 256 + tid;
        g_W2h[idx] = __float2half_rn(W2[idx]);
    } else if (bi < 3584) {
        int idx = (bi - 2048) * 256 + tid;
        g_Woh[idx] = __float2half_rn(Wo[idx]);
    } else if (bi < 3968) {
        int idx = bi - 3584;
        int i = idx >> 6;
        int rem = idx & 63;
        int m0 = (rem & 7) * 32, kp0 = (rem >> 3) * 32;
        int tx = tid & 31, ty = tid >> 5;
        const float* src = Wv + i * 65536;
#pragma unroll
        for (int j = 0; j < 4; j++) {
            int row = ty + j * 8;
            t[row][tx] = src[(m0 + row) * 256 + kp0 + tx];
        }
        __syncthreads();
#pragma unroll
        for (int j = 0; j < 4; j++) {
            int row = ty + j * 8;   // kp-local
            g_Wvt[i * 65536 + (kp0 + row) * 256 + m0 + tx] = __float2half_rn(t[tx][row]);
        }
    } else {
        int i = bi - 3968, e = tid;
        const float* w = Wo + i * 65536 + e * 256;
        const float* b = bv + i * 256;
        float a0 = 0.f, a1 = 0.f, a2 = 0.f, a3 = 0.f;
#pragma unroll 4
        for (int m = 0; m < 256; m += 4) {
            a0 += w[m + 0] * b[m + 0];
            a1 += w[m + 1] * b[m + 1];
            a2 += w[m + 2] * b[m + 2];
            a3 += w[m + 3] * b[m + 3];
        }
        g_cvec[i * 256 + e] = bo[i * 256 + e] + (a0 + a1) + (a2 + a3);
    }
}

// ============================================================================
// SMEM layouts
// ============================================================================
#define SM_A0 0
#define SM_A1 16384
#define SM_B0 32768
#define SM_B1 49152
#define SMEM_G 65536
// small-tile (64x64) mma kernels
#define SMM_A0 0
#define SMM_A1 8192
#define SMM_B0 16384
#define SMM_B1 24576
#define SMEM_M 32768

// ============================================================================
// k_MmmaB: merged launch, grid 608 x 128 threads
//   blocks [0,96):   M_i[e][kp] = Woh_i @ Wvt_i (64x64 tiles, K=256) -> g_Bc fp16
//   blocks [96,608): b1eff[n] = b1[n] + sum_j csum[j]*W1[n][j] (fp32 reduction)
// Both depend only on k_prep.
// ============================================================================
__global__ void __launch_bounds__(128)
k_MmmaB(const float* __restrict__ W1, const float* __restrict__ b1) {
    extern __shared__ char smem[];
    const int tid = threadIdx.x;
    const int bi = blockIdx.x;

    if (bi >= 96) {
        // ---------- b1eff branch: one block per n, 128-thread reduction ----------
        const int n = bi - 96;
        float p = 0.f;
#pragma unroll
        for (int jj = 0; jj < 6; jj++) {
            int j = jj * 128 + tid;
            int q = j >> 8, e = j & 255;
            float cs = g_cvec[(2 * q) * 256 + e] + g_cvec[(2 * q + 1) * 256 + e];
            p += cs * W1[n * KIN + j];
        }
        float* red = (float*)smem;
        red[tid] = p;
        __syncthreads();
#pragma unroll
        for (int s = 64; s > 0; s >>= 1) {
            if (tid < s) red[tid] += red[tid + s];
            __syncthreads();
        }
        if (tid == 0) g_b1eff[n] = b1[n] + red[0];
        return;
    }

    // ---------- M-GEMM branch ----------
    const uint32_t sb = smem_u32(smem);
    const int wid = tid >> 5, lane = tid & 31;
    const int kp0c = (bi & 3) * 64;
    const int e0c  = ((bi >> 2) & 3) * 64;
    const int i    = bi >> 4;
    const int wm = (wid >> 1) * 32;
    const int wn = (wid & 1) * 32;
    // i -> (r, qi): midx 0->(1,0) 1->(2,0) 2->(0,0) 3->(2,1) 4->(0,1) 5->(1,1)
    const int r  = (i == 0) ? 1 : (i == 1) ? 2 : (i == 2) ? 0 : (i == 3) ? 2 : (i == 4) ? 0 : 1;
    const int qi = (i <= 2) ? 0 : 1;
    const __half* Asrc = g_Woh + i * 65536;
    const __half* Bsrc = g_Wvt + i * 65536;

    float acc[2][4][4];
#pragma unroll
    for (int a = 0; a < 2; a++)
#pragma unroll
        for (int j = 0; j < 4; j++)
#pragma unroll
            for (int v = 0; v < 4; v++) acc[a][j][v] = 0.f;

    // prologue buffer 0 (4 x 16B per thread per operand)
    {
#pragma unroll
        for (int a = 0; a < 4; a++) {
            int idx = a * 128 + tid;
            int row = idx >> 3, c = idx & 7;
            cp_async16(sb + SMM_A0 + swz(row, c * 8), Asrc + (size_t)(e0c + row) * 256 + c * 8);
            cp_async16(sb + SMM_B0 + swz(row, c * 8), Bsrc + (size_t)(kp0c + row) * 256 + c * 8);
        }
        cp_commit();
        cp_wait0();
        __syncthreads();
    }

    const int NITER = 4;
    for (int kc = 0; kc < NITER; kc++) {
        const uint32_t Abase = sb + (kc & 1 ? SMM_A1 : SMM_A0);
        const uint32_t Bbase = sb + (kc & 1 ? SMM_B1 : SMM_B0);
        const int nxt = kc + 1;

        if (nxt < NITER) {
            uint32_t AbaseN = sb + (nxt & 1 ? SMM_A1 : SMM_A0);
            uint32_t BbaseN = sb + (nxt & 1 ? SMM_B1 : SMM_B0);
#pragma unroll
            for (int a = 0; a < 4; a++) {
                int idx = a * 128 + tid;
                int row = idx >> 3, c = idx & 7;
                cp_async16(AbaseN + swz(row, c * 8),
                           Asrc + (size_t)(e0c + row) * 256 + nxt * 64 + c * 8);
                cp_async16(BbaseN + swz(row, c * 8),
                           Bsrc + (size_t)(kp0c + row) * 256 + nxt * 64 + c * 8);
            }
            cp_commit();
        }

#pragma unroll
        for (int ks = 0; ks < 64; ks += 16) {
            uint32_t a[2][4], b[8];
#pragma unroll
            for (int t = 0; t < 2; t++) {
                uint32_t row = wm + t * 16 + (lane & 15);
                uint32_t kk  = ks + (lane >> 4) * 8;
                ldm_x4(a[t][0], a[t][1], a[t][2], a[t][3], Abase + swz(row, kk));
            }
#pragma unroll
            for (int h = 0; h < 2; h++) {
                int g = lane >> 3, ri = lane & 7;
                uint32_t nrow = wn + h * 16 + (g >> 1) * 8 + ri;
                uint32_t kk   = ks + (g & 1) * 8;
                ldm_x4(b[h * 4 + 0], b[h * 4 + 1], b[h * 4 + 2], b[h * 4 + 3],
                       Bbase + swz(nrow, kk));
            }
#pragma unroll
            for (int mt = 0; mt < 2; mt++)
#pragma unroll
                for (int nt = 0; nt < 4; nt++)
                    mma16816(acc[mt][nt], a[mt][0], a[mt][1], a[mt][2], a[mt][3],
                             b[nt * 2], b[nt * 2 + 1]);
        }

        if (nxt < NITER) cp_wait0();
        __syncthreads();
    }

    // epilogue: g_Bc[r][kp][qi*256 + e] = fp16(M[e][kp])
    __half* dst = g_Bc + r * 131072 + qi * 256;
#pragma unroll
    for (int mt = 0; mt < 2; mt++) {
#pragma unroll
        for (int nt = 0; nt < 4; nt++) {
            int kp = kp0c + wn + nt * 8 + (lane & 3) * 2;
            int e  = e0c + wm + mt * 16 + (lane >> 2);
            dst[(size_t)kp * 512 + e]           = __float2half_rn(acc[mt][nt][0]);
            dst[(size_t)(kp + 1) * 512 + e]     = __float2half_rn(acc[mt][nt][1]);
            dst[(size_t)kp * 512 + e + 8]       = __float2half_rn(acc[mt][nt][2]);
            dst[(size_t)(kp + 1) * 512 + e + 8] = __float2half_rn(acc[mt][nt][3]);
        }
    }
}

// ============================================================================
// k_B1mma: per r, fold[n][kp] = W1h[n, qe-sel] @ Bc[r]^T + W1 (64x64 tiles)
// grid (4 kp-chunks, 8 n-chunks, 3 r), 128 thr; K=512 (two q blocks of 256)
// ============================================================================
__global__ void __launch_bounds__(128)
k_B1mma(const float* __restrict__ W1) {
    extern __shared__ char smem[];
    const uint32_t sb = smem_u32(smem);
    const int tid = threadIdx.x;
    const int wid = tid >> 5, lane = tid & 31;
    const int m0 = blockIdx.y * 64;         // n-dim (rows of W1)
    const int n0 = blockIdx.x * 64;         // kp-dim
    const int r  = blockIdx.z;
    const int wm = (wid >> 1) * 32;
    const int wn = (wid & 1) * 32;
    const int q0 = (r == 0) ? 1 : 0;
    const int q1 = (r == 2) ? 1 : 2;
    const __half* Bsrc = g_Bc + r * 131072;

    float acc[2][4][4];
#pragma unroll
    for (int i = 0; i < 2; i++)
#pragma unroll
        for (int j = 0; j < 4; j++)
#pragma unroll
            for (int v = 0; v < 4; v++) acc[i][j][v] = 0.f;

    // prologue: buffer 0 (kc = 0 -> q = q0, colpart 0)
    {
#pragma unroll
        for (int i = 0; i < 4; i++) {
            int idx = i * 128 + tid;
            int row = idx >> 3, c = idx & 7;
            cp_async16(sb + SMM_A0 + swz(row, c * 8),
                       g_W1h + (size_t)(m0 + row) * KIN + q0 * 256 + c * 8);
            cp_async16(sb + SMM_B0 + swz(row, c * 8),
                       Bsrc + (size_t)(n0 + row) * 512 + c * 8);
        }
        cp_commit();
        cp_wait0();
        __syncthreads();
    }

    const int NITER = 8;
    for (int kc = 0; kc < NITER; kc++) {
        const uint32_t Abase = sb + (kc & 1 ? SMM_A1 : SMM_A0);
        const uint32_t Bbase = sb + (kc & 1 ? SMM_B1 : SMM_B0);
        const int nxt = kc + 1;

        if (nxt < NITER) {
            uint32_t AbaseN = sb + (nxt & 1 ? SMM_A1 : SMM_A0);
            uint32_t BbaseN = sb + (nxt & 1 ? SMM_B1 : SMM_B0);
            int q = (nxt >> 2) ? q1 : q0;
            int colbase = q * 256 + (nxt & 3) * 64;
#pragma unroll
            for (int i = 0; i < 4; i++) {
                int idx = i * 128 + tid;
                int row = idx >> 3, c = idx & 7;
                cp_async16(AbaseN + swz(row, c * 8),
                           g_W1h + (size_t)(m0 + row) * KIN + colbase + c * 8);
                cp_async16(BbaseN + swz(row, c * 8),
                           Bsrc + (size_t)(n0 + row) * 512 + nxt * 64 + c * 8);
            }
            cp_commit();
        }

#pragma unroll
        for (int ks = 0; ks < 64; ks += 16) {
            uint32_t a[2][4], b[8];
#pragma unroll
            for (int t = 0; t < 2; t++) {
                uint32_t row = wm + t * 16 + (lane & 15);
                uint32_t kk  = ks + (lane >> 4) * 8;
                ldm_x4(a[t][0], a[t][1], a[t][2], a[t][3], Abase + swz(row, kk));
            }
#pragma unroll
            for (int h = 0; h < 2; h++) {
                int g = lane >> 3, ri = lane & 7;
                uint32_t nrow = wn + h * 16 + (g >> 1) * 8 + ri;
                uint32_t kk   = ks + (g & 1) * 8;
                ldm_x4(b[h * 4 + 0], b[h * 4 + 1], b[h * 4 + 2], b[h * 4 + 3],
                       Bbase + swz(nrow, kk));
            }
#pragma unroll
            for (int mt = 0; mt < 2; mt++)
#pragma unroll
                for (int nt = 0; nt < 4; nt++)
                    mma16816(acc[mt][nt], a[mt][0], a[mt][1], a[mt][2], a[mt][3],
                             b[nt * 2], b[nt * 2 + 1]);
        }

        if (nxt < NITER) cp_wait0();
        __syncthreads();
    }

    // epilogue: B1h[n][r*256+kp] = fp16(W1[n][r*256+kp] + acc)
#pragma unroll
    for (int mt = 0; mt < 2; mt++) {
#pragma unroll
        for (int nt = 0; nt < 4; nt++) {
            int kp = n0 + wn + nt * 8 + (lane & 3) * 2;
            int nrow0 = m0 + wm + mt * 16 + (lane >> 2);
            size_t base0 = (size_t)nrow0 * KIN + r * 256 + kp;
            size_t base1 = (size_t)(nrow0 + 8) * KIN + r * 256 + kp;
            __half2 h01 = __floats2half2_rn(W1[base0] + acc[mt][nt][0],
                                            W1[base0 + 1] + acc[mt][nt][1]);
            __half2 h23 = __floats2half2_rn(W1[base1] + acc[mt][nt][2],
                                            W1[base1 + 1] + acc[mt][nt][3]);
            *(__half2*)(g_B1h + base0) = h01;
            *(__half2*)(g_B1h + base1) = h23;
        }
    }
}

// ============================================================================
// GEMM1 (R6 winner): hidden[B,512] = relu(X[B,768] @ B1h^T + b1eff)
// 256 thr, tile 128x128, warp tile 64x32, K-chunk 64, double-buffered, occ 2
// ============================================================================
__global__ void __launch_bounds__(256, 2)
gemm1(const float* __restrict__ gE, const float* __restrict__ dE,
      const float* __restrict__ cE) {
    extern __shared__ char smem[];
    const uint32_t sb = smem_u32(smem);
    const int tid = threadIdx.x;
    const int wid = tid >> 5, lane = tid & 31;
    const int m0 = blockIdx.y * 128;
    const int n0 = blockIdx.x * 128;
    const int wm = (wid >> 2) * 64;
    const int wn = (wid & 3) * 32;
    const float* srcs[3] = {gE, dE, cE};

    float acc[4][4][4];
#pragma unroll
    for (int i = 0; i < 4; i++)
#pragma unroll
        for (int j = 0; j < 4; j++)
#pragma unroll
            for (int v = 0; v < 4; v++) acc[i][j][v] = 0.f;

    const int a_row[8] = { (0*256+tid) >> 4, (1*256+tid) >> 4, (2*256+tid) >> 4, (3*256+tid) >> 4,
                           (4*256+tid) >> 4, (5*256+tid) >> 4, (6*256+tid) >> 4, (7*256+tid) >> 4 };
    const int a_c4 = tid & 15;

    uint2 ah[8];   // A fragment converted to fp16 at load time

    // prologue: buffer 0 (kc = 0)
    {
        const float* src = srcs[0] + (size_t)m0 * 256;
#pragma unroll
        for (int i = 0; i < 8; i++) {
            float4 f = *(const float4*)(src + (size_t)a_row[i] * 256 + a_c4 * 4);
            __half2 h0 = __floats2half2_rn(f.x, f.y);
            __half2 h1 = __floats2half2_rn(f.z, f.w);
            ah[i].x = *(uint32_t*)&h0;
            ah[i].y = *(uint32_t*)&h1;
        }
#pragma unroll
        for (int i = 0; i < 8; i++)
            *(uint2*)(smem + SM_A0 + swz(a_row[i], a_c4 * 4)) = ah[i];
#pragma unroll
        for (int i = 0; i < 4; i++) {
            int idx = i * 256 + tid;
            int row = idx >> 3, c = idx & 7;
            cp_async16(sb + SM_B0 + swz(row, c * 8), g_B1h + (size_t)(n0 + row) * KIN + c * 8);
        }
        cp_commit();
        cp_wait0();
        __syncthreads();
    }

    const int NITER = 12;
    for (int kc = 0; kc < NITER; kc++) {
        const uint32_t Abase = sb + (kc & 1 ? SM_A1 : SM_A0);
        const uint32_t Bbase = sb + (kc & 1 ? SM_B1 : SM_B0);
        const int nxt = kc + 1;
        const uint32_t AbaseN = sb + (nxt & 1 ? SM_A1 : SM_A0);
        const uint32_t BbaseN = sb + (nxt & 1 ? SM_B1 : SM_B0);

        if (nxt < NITER) {
            const float* src = srcs[nxt >> 2] + (size_t)m0 * 256 + (nxt & 3) * 64;
#pragma unroll
            for (int i = 0; i < 8; i++) {
                float4 f = *(const float4*)(src + (size_t)a_row[i] * 256 + a_c4 * 4);
                __half2 h0 = __floats2half2_rn(f.x, f.y);
                __half2 h1 = __floats2half2_rn(f.z, f.w);
                ah[i].x = *(uint32_t*)&h0;
                ah[i].y = *(uint32_t*)&h1;
            }
#pragma unroll
            for (int i = 0; i < 4; i++) {
                int idx = i * 256 + tid;
                int row = idx >> 3, c = idx & 7;
                cp_async16(BbaseN + swz(row, c * 8),
                           g_B1h + (size_t)(n0 + row) * KIN + nxt * 64 + c * 8);
            }
            cp_commit();
        }

        // compute on current buffers
#pragma unroll
        for (int ks = 0; ks < 64; ks += 16) {
            uint32_t a[4][4], b[8];
#pragma unroll
            for (int t = 0; t < 4; t++) {
                uint32_t row = wm + t * 16 + (lane & 15);
                uint32_t kk  = ks + (lane >> 4) * 8;
                ldm_x4(a[t][0], a[t][1], a[t][2], a[t][3], Abase + swz(row, kk));
            }
#pragma unroll
            for (int h = 0; h < 2; h++) {
                int g = lane >> 3, ri = lane & 7;
                uint32_t nrow = wn + h * 16 + (g >> 1) * 8 + ri;
                uint32_t kk   = ks + (g & 1) * 8;
                ldm_x4(b[h * 4 + 0], b[h * 4 + 1], b[h * 4 + 2], b[h * 4 + 3],
                       Bbase + swz(nrow, kk));
            }
#pragma unroll
            for (int mt = 0; mt < 4; mt++)
#pragma unroll
                for (int nt = 0; nt < 4; nt++)
                    mma16816(acc[mt][nt], a[mt][0], a[mt][1], a[mt][2], a[mt][3],
                             b[nt * 2], b[nt * 2 + 1]);
        }

        if (nxt < NITER) {
#pragma unroll
            for (int i = 0; i < 8; i++)
                *(uint2*)((char*)smem + (AbaseN - sb) + swz(a_row[i], a_c4 * 4)) = ah[i];
            cp_wait0();
        }
        __syncthreads();
    }

    // epilogue: relu(acc + b1eff) -> fp16 g_H
#pragma unroll
    for (int mt = 0; mt < 4; mt++) {
#pragma unroll
        for (int nt = 0; nt < 4; nt++) {
            int n = n0 + wn + nt * 8 + (lane & 3) * 2;
            float bia0 = g_b1eff[n], bia1 = g_b1eff[n + 1];
            int r0 = m0 + wm + mt * 16 + (lane >> 2);
            float v0 = fmaxf(acc[mt][nt][0] + bia0, 0.f);
            float v1 = fmaxf(acc[mt][nt][1] + bia1, 0.f);
            float v2 = fmaxf(acc[mt][nt][2] + bia0, 0.f);
            float v3 = fmaxf(acc[mt][nt][3] + bia1, 0.f);
            __half2 h01 = __floats2half2_rn(v0, v1);
            __half2 h23 = __floats2half2_rn(v2, v3);
            *(__half2*)(g_H + (size_t)r0 * HIDN + n)       = h01;
            *(__half2*)(g_H + (size_t)(r0 + 8) * HIDN + n) = h23;
        }
    }
}

// ============================================================================
// GEMM2 (R6 winner): out[B,256] = g_H[B,512] @ W2h^T + b2, fp32 out, occ 2
// ============================================================================
__global__ void __launch_bounds__(256, 2)
gemm2(const float* __restrict__ b2, float* __restrict__ out) {
    extern __shared__ char smem[];
    const uint32_t sb = smem_u32(smem);
    const int tid = threadIdx.x;
    const int wid = tid >> 5, lane = tid & 31;
    const int m0 = blockIdx.y * 128;
    const int n0 = blockIdx.x * 128;
    const int wm = (wid >> 2) * 64;
    const int wn = (wid & 3) * 32;

    float acc[4][4][4];
#pragma unroll
    for (int i = 0; i < 4; i++)
#pragma unroll
        for (int j = 0; j < 4; j++)
#pragma unroll
            for (int v = 0; v < 4; v++) acc[i][j][v] = 0.f;

    // prologue buffer 0
    {
#pragma unroll
        for (int i = 0; i < 4; i++) {
            int idx = i * 256 + tid;
            int row = idx >> 3, c = idx & 7;
            cp_async16(sb + SM_A0 + swz(row, c * 8), g_H + (size_t)(m0 + row) * HIDN + c * 8);
            cp_async16(sb + SM_B0 + swz(row, c * 8), g_W2h + (size_t)(n0 + row) * HIDN + c * 8);
        }
        cp_commit();
        cp_wait0();
        __syncthreads();
    }

    const int NITER = 8;
    for (int kc = 0; kc < NITER; kc++) {
        const uint32_t Abase = sb + (kc & 1 ? SM_A1 : SM_A0);
        const uint32_t Bbase = sb + (kc & 1 ? SM_B1 : SM_B0);
        const int nxt = kc + 1;

        if (nxt < NITER) {
            uint32_t AbaseN = sb + (nxt & 1 ? SM_A1 : SM_A0);
            uint32_t BbaseN = sb + (nxt & 1 ? SM_B1 : SM_B0);
#pragma unroll
            for (int i = 0; i < 4; i++) {
                int idx = i * 256 + tid;
                int row = idx >> 3, c = idx & 7;
                cp_async16(AbaseN + swz(row, c * 8),
                           g_H + (size_t)(m0 + row) * HIDN + nxt * 64 + c * 8);
                cp_async16(BbaseN + swz(row, c * 8),
                           g_W2h + (size_t)(n0 + row) * HIDN + nxt * 64 + c * 8);
            }
            cp_commit();
        }

#pragma unroll
        for (int ks = 0; ks < 64; ks += 16) {
            uint32_t a[4][4], b[8];
#pragma unroll
            for (int t = 0; t < 4; t++) {
                uint32_t row = wm + t * 16 + (lane & 15);
                uint32_t kk  = ks + (lane >> 4) * 8;
                ldm_x4(a[t][0], a[t][1], a[t][2], a[t][3], Abase + swz(row, kk));
            }
#pragma unroll
            for (int h = 0; h < 2; h++) {
                int g = lane >> 3, ri = lane & 7;
                uint32_t nrow = wn + h * 16 + (g >> 1) * 8 + ri;
                uint32_t kk   = ks + (g & 1) * 8;
                ldm_x4(b[h * 4 + 0], b[h * 4 + 1], b[h * 4 + 2], b[h * 4 + 3],
                       Bbase + swz(nrow, kk));
            }
#pragma unroll
            for (int mt = 0; mt < 4; mt++)
#pragma unroll
                for (int nt = 0; nt < 4; nt++)
                    mma16816(acc[mt][nt], a[mt][0], a[mt][1], a[mt][2], a[mt][3],
                             b[nt * 2], b[nt * 2 + 1]);
        }

        if (nxt < NITER) cp_wait0();
        __syncthreads();
    }

    // epilogue: acc + b2 -> fp32 out
#pragma unroll
    for (int mt = 0; mt < 4; mt++) {
#pragma unroll
        for (int nt = 0; nt < 4; nt++) {
            int n = n0 + wn + nt * 8 + (lane & 3) * 2;
            float bia0 = b2[n], bia1 = b2[n + 1];
            int r0 = m0 + wm + mt * 16 + (lane >> 2);
            float2 o01 = { acc[mt][nt][0] + bia0, acc[mt][nt][1] + bia1 };
            float2 o23 = { acc[mt][nt][2] + bia0, acc[mt][nt][3] + bia1 };
            *(float2*)(out + (size_t)r0 * EDIM + n)       = o01;
            *(float2*)(out + (size_t)(r0 + 8) * EDIM + n) = o23;
        }
    }
}

// ============================================================================
// kernel_launch
// Input order: g, d, c, Wq, Wk, Wv, bq, bk, bv, Wo, bo, W1, b1, W2, b2
// ============================================================================
extern "C" void kernel_launch(void* const* d_in, const int* in_sizes, int n_in,
                              void* d_out, int out_size) {
    const float* g  = (const float*)d_in[0];
    const float* dd = (const float*)d_in[1];
    const float* cc = (const float*)d_in[2];
    const float* Wv = (const float*)d_in[5];
    const float* bv = (const float*)d_in[8];
    const float* Wo = (const float*)d_in[9];
    const float* bo = (const float*)d_in[10];
    const float* W1 = (const float*)d_in[11];
    const float* b1 = (const float*)d_in[12];
    const float* W2 = (const float*)d_in[13];
    const float* b2 = (const float*)d_in[14];
    const int B = in_sizes[0] / EDIM;

    cudaFuncSetAttribute(k_MmmaB, cudaFuncAttributeMaxDynamicSharedMemorySize, SMEM_M);
    cudaFuncSetAttribute(k_B1mma, cudaFuncAttributeMaxDynamicSharedMemorySize, SMEM_M);
    cudaFuncSetAttribute(gemm1,   cudaFuncAttributeMaxDynamicSharedMemorySize, SMEM_G);
    cudaFuncSetAttribute(gemm2,   cudaFuncAttributeMaxDynamicSharedMemorySize, SMEM_G);

    // Precompute chain: 3 launches (was 4)
    k_prep  <<<3974, 256>>>(W1, W2, Wo, Wv, bv, bo);  // fp16 conv + transpose + cvec
    k_MmmaB <<<608, 128, SMEM_M>>>(W1, b1);           // M GEMMs (96) + b1eff (512) merged
    k_B1mma <<<dim3(4, 8, 3), 128, SMEM_M>>>(W1);     // fold (+W1 -> fp16)

    gemm1<<<dim3(4, B / 128), 256, SMEM_G>>>(g, dd, cc);
    gemm2<<<dim3(2, B / 128), 256, SMEM_G>>>(b2, (float*)d_out);
}

// round 15
// speedup vs baseline: 1.0721x; 1.0010x over previous
#include <cuda_runtime.h>
#include <cuda_fp16.h>
#include <cstdint>

// ============================================================================
// Problem constants
// ============================================================================
#define EDIM 256      // E
#define HIDN 512      // 2E
#define KIN  768      // 3E
#define BTOT 131072

// ============================================================================
// Device scratch (allocation-free rule: __device__ globals)
// ============================================================================
__device__ float  g_cvec[6 * EDIM];                      // c_i = Wo_i @ bv_i + bo_i
__device__ float  g_b1eff[HIDN];                         // b1 + Kvec @ W1^T
__device__ __align__(16) __half g_W1h[HIDN * KIN];       // W1 fp16
__device__ __align__(16) __half g_Woh[6 * EDIM * EDIM];  // Wo fp16 [i][e][m]
__device__ __align__(16) __half g_Wvt[6 * EDIM * EDIM];  // Wv fp16 transposed [i][kp][m]
__device__ __align__(16) __half g_Bc[3 * EDIM * HIDN];   // repacked M: [r][kp][qe] fp16
__device__ __align__(16) __half g_B1h[HIDN * KIN];       // folded W1, fp16 [N=512][K=768]
__device__ __align__(16) __half g_W2h[EDIM * HIDN];      // W2 fp16 [N=256][K=512]
__device__ __align__(16) __half g_H[(size_t)BTOT * HIDN];// hidden fp16 [131072][512]

// ============================================================================
// PTX helpers (baseline sm_80+ features only: mma.sync / ldmatrix / cp.async)
// ============================================================================
__device__ __forceinline__ uint32_t smem_u32(const void* p) {
    uint32_t a;
    asm("{ .reg .u64 t; cvta.to.shared.u64 t, %1; cvt.u32.u64 %0, t; }" : "=r"(a) : "l"(p));
    return a;
}

__device__ __forceinline__ void cp_async16(uint32_t saddr, const void* gaddr) {
    asm volatile("cp.async.cg.shared.global [%0], [%1], 16;" :: "r"(saddr), "l"(gaddr));
}
__device__ __forceinline__ void cp_commit() { asm volatile("cp.async.commit_group;" ::: "memory"); }
__device__ __forceinline__ void cp_wait0()  { asm volatile("cp.async.wait_group 0;" ::: "memory"); }
__device__ __forceinline__ void cp_wait1()  { asm volatile("cp.async.wait_group 1;" ::: "memory"); }

__device__ __forceinline__ void ldm_x4(uint32_t& r0, uint32_t& r1, uint32_t& r2, uint32_t& r3,
                                       uint32_t addr) {
    asm volatile("ldmatrix.sync.aligned.m8n8.x4.shared.b16 {%0,%1,%2,%3}, [%4];"
                 : "=r"(r0), "=r"(r1), "=r"(r2), "=r"(r3) : "r"(addr));
}

__device__ __forceinline__ void mma16816(float* c, uint32_t a0, uint32_t a1, uint32_t a2,
                                         uint32_t a3, uint32_t b0, uint32_t b1) {
    asm volatile(
        "mma.sync.aligned.m16n8k16.row.col.f32.f16.f16.f32 "
        "{%0,%1,%2,%3}, {%4,%5,%6,%7}, {%8,%9}, {%0,%1,%2,%3};"
        : "+f"(c[0]), "+f"(c[1]), "+f"(c[2]), "+f"(c[3])
        : "r"(a0), "r"(a1), "r"(a2), "r"(a3), "r"(b0), "r"(b1));
}

// XOR swizzle for [rows][64 halves] tiles (128B rows, 16B units, 8-way)
__device__ __forceinline__ uint32_t swz(uint32_t row, uint32_t k) {
    return row * 128u + ((((k >> 3) ^ (row & 7)) << 4) | ((k & 7) * 2u));
}

// ============================================================================
// k_prep: merged W1/W2/Wo->fp16, Wv transpose->fp16, cvec. grid 3974 x 256
// ============================================================================
__global__ void __launch_bounds__(256) k_prep(const float* __restrict__ W1,
                                              const float* __restrict__ W2,
                                              const float* __restrict__ Wo,
                                              const float* __restrict__ Wv,
                                              const float* __restrict__ bv,
                                              const float* __restrict__ bo) {
    __shared__ float t[32][33];
    const int bi = blockIdx.x;
    const int tid = threadIdx.x;
    if (bi < 1536) {
        int idx = bi * 256 + tid;
        g_W1h[idx] = __float2half_rn(W1[idx]);
    } else if (bi < 2048) {
        int idx = (bi - 1536) * 256 + tid;
        g_W2h[idx] = __float2half_rn(W2[idx]);
    } else if (bi < 3584) {
        int idx = (bi - 2048) * 256 + tid;
        g_Woh[idx] = __float2half_rn(Wo[idx]);
    } else if (bi < 3968) {
        int idx = bi - 3584;
        int i = idx >> 6;
        int rem = idx & 63;
        int m0 = (rem & 7) * 32, kp0 = (rem >> 3) * 32;
        int tx = tid & 31, ty = tid >> 5;
        const float* src = Wv + i * 65536;
#pragma unroll
        for (int j = 0; j < 4; j++) {
            int row = ty + j * 8;
            t[row][tx] = src[(m0 + row) * 256 + kp0 + tx];
        }
        __syncthreads();
#pragma unroll
        for (int j = 0; j < 4; j++) {
            int row = ty + j * 8;   // kp-local
            g_Wvt[i * 65536 + (kp0 + row) * 256 + m0 + tx] = __float2half_rn(t[tx][row]);
        }
    } else {
        int i = bi - 3968, e = tid;
        const float* w = Wo + i * 65536 + e * 256;
        const float* b = bv + i * 256;
        float a0 = 0.f, a1 = 0.f, a2 = 0.f, a3 = 0.f;
#pragma unroll 4
        for (int m = 0; m < 256; m += 4) {
            a0 += w[m + 0] * b[m + 0];
            a1 += w[m + 1] * b[m + 1];
            a2 += w[m + 2] * b[m + 2];
            a3 += w[m + 3] * b[m + 3];
        }
        g_cvec[i * 256 + e] = bo[i * 256 + e] + (a0 + a1) + (a2 + a3);
    }
}

// ============================================================================
// SMEM layouts
// ============================================================================
#define SM_A0 0
#define SM_A1 16384
#define SM_B0 32768
#define SM_B1 49152
#define SMEM_G 65536
// gemm2 3-stage: A s*16K (s=0..2), B 48K + s*16K
#define SMEM_G2 98304
// small-tile (64x64) mma kernels
#define SMM_A0 0
#define SMM_A1 8192
#define SMM_B0 16384
#define SMM_B1 24576
#define SMEM_M 32768

// ============================================================================
// k_MmmaB: merged launch, grid 608 x 128 threads
//   blocks [0,96):   M_i[e][kp] = Woh_i @ Wvt_i (64x64 tiles, K=256) -> g_Bc fp16
//   blocks [96,608): b1eff[n] reduction
// ============================================================================
__global__ void __launch_bounds__(128)
k_MmmaB(const float* __restrict__ W1, const float* __restrict__ b1) {
    extern __shared__ char smem[];
    const int tid = threadIdx.x;
    const int bi = blockIdx.x;

    if (bi >= 96) {
        const int n = bi - 96;
        float p = 0.f;
#pragma unroll
        for (int jj = 0; jj < 6; jj++) {
            int j = jj * 128 + tid;
            int q = j >> 8, e = j & 255;
            float cs = g_cvec[(2 * q) * 256 + e] + g_cvec[(2 * q + 1) * 256 + e];
            p += cs * W1[n * KIN + j];
        }
        float* red = (float*)smem;
        red[tid] = p;
        __syncthreads();
#pragma unroll
        for (int s = 64; s > 0; s >>= 1) {
            if (tid < s) red[tid] += red[tid + s];
            __syncthreads();
        }
        if (tid == 0) g_b1eff[n] = b1[n] + red[0];
        return;
    }

    const uint32_t sb = smem_u32(smem);
    const int wid = tid >> 5, lane = tid & 31;
    const int kp0c = (bi & 3) * 64;
    const int e0c  = ((bi >> 2) & 3) * 64;
    const int i    = bi >> 4;
    const int wm = (wid >> 1) * 32;
    const int wn = (wid & 1) * 32;
    const int r  = (i == 0) ? 1 : (i == 1) ? 2 : (i == 2) ? 0 : (i == 3) ? 2 : (i == 4) ? 0 : 1;
    const int qi = (i <= 2) ? 0 : 1;
    const __half* Asrc = g_Woh + i * 65536;
    const __half* Bsrc = g_Wvt + i * 65536;

    float acc[2][4][4];
#pragma unroll
    for (int a = 0; a < 2; a++)
#pragma unroll
        for (int j = 0; j < 4; j++)
#pragma unroll
            for (int v = 0; v < 4; v++) acc[a][j][v] = 0.f;

    {
#pragma unroll
        for (int a = 0; a < 4; a++) {
            int idx = a * 128 + tid;
            int row = idx >> 3, c = idx & 7;
            cp_async16(sb + SMM_A0 + swz(row, c * 8), Asrc + (size_t)(e0c + row) * 256 + c * 8);
            cp_async16(sb + SMM_B0 + swz(row, c * 8), Bsrc + (size_t)(kp0c + row) * 256 + c * 8);
        }
        cp_commit();
        cp_wait0();
        __syncthreads();
    }

    const int NITER = 4;
    for (int kc = 0; kc < NITER; kc++) {
        const uint32_t Abase = sb + (kc & 1 ? SMM_A1 : SMM_A0);
        const uint32_t Bbase = sb + (kc & 1 ? SMM_B1 : SMM_B0);
        const int nxt = kc + 1;

        if (nxt < NITER) {
            uint32_t AbaseN = sb + (nxt & 1 ? SMM_A1 : SMM_A0);
            uint32_t BbaseN = sb + (nxt & 1 ? SMM_B1 : SMM_B0);
#pragma unroll
            for (int a = 0; a < 4; a++) {
                int idx = a * 128 + tid;
                int row = idx >> 3, c = idx & 7;
                cp_async16(AbaseN + swz(row, c * 8),
                           Asrc + (size_t)(e0c + row) * 256 + nxt * 64 + c * 8);
                cp_async16(BbaseN + swz(row, c * 8),
                           Bsrc + (size_t)(kp0c + row) * 256 + nxt * 64 + c * 8);
            }
            cp_commit();
        }

#pragma unroll
        for (int ks = 0; ks < 64; ks += 16) {
            uint32_t a[2][4], b[8];
#pragma unroll
            for (int t = 0; t < 2; t++) {
                uint32_t row = wm + t * 16 + (lane & 15);
                uint32_t kk  = ks + (lane >> 4) * 8;
                ldm_x4(a[t][0], a[t][1], a[t][2], a[t][3], Abase + swz(row, kk));
            }
#pragma unroll
            for (int h = 0; h < 2; h++) {
                int g = lane >> 3, ri = lane & 7;
                uint32_t nrow = wn + h * 16 + (g >> 1) * 8 + ri;
                uint32_t kk   = ks + (g & 1) * 8;
                ldm_x4(b[h * 4 + 0], b[h * 4 + 1], b[h * 4 + 2], b[h * 4 + 3],
                       Bbase + swz(nrow, kk));
            }
#pragma unroll
            for (int mt = 0; mt < 2; mt++)
#pragma unroll
                for (int nt = 0; nt < 4; nt++)
                    mma16816(acc[mt][nt], a[mt][0], a[mt][1], a[mt][2], a[mt][3],
                             b[nt * 2], b[nt * 2 + 1]);
        }

        if (nxt < NITER) cp_wait0();
        __syncthreads();
    }

    __half* dst = g_Bc + r * 131072 + qi * 256;
#pragma unroll
    for (int mt = 0; mt < 2; mt++) {
#pragma unroll
        for (int nt = 0; nt < 4; nt++) {
            int kp = kp0c + wn + nt * 8 + (lane & 3) * 2;
            int e  = e0c + wm + mt * 16 + (lane >> 2);
            dst[(size_t)kp * 512 + e]           = __float2half_rn(acc[mt][nt][0]);
            dst[(size_t)(kp + 1) * 512 + e]     = __float2half_rn(acc[mt][nt][1]);
            dst[(size_t)kp * 512 + e + 8]       = __float2half_rn(acc[mt][nt][2]);
            dst[(size_t)(kp + 1) * 512 + e + 8] = __float2half_rn(acc[mt][nt][3]);
        }
    }
}

// ============================================================================
// k_B1mma: per r, fold[n][kp] = W1h[n, qe-sel] @ Bc[r]^T + W1 (64x64 tiles)
// ============================================================================
__global__ void __launch_bounds__(128)
k_B1mma(const float* __restrict__ W1) {
    extern __shared__ char smem[];
    const uint32_t sb = smem_u32(smem);
    const int tid = threadIdx.x;
    const int wid = tid >> 5, lane = tid & 31;
    const int m0 = blockIdx.y * 64;
    const int n0 = blockIdx.x * 64;
    const int r  = blockIdx.z;
    const int wm = (wid >> 1) * 32;
    const int wn = (wid & 1) * 32;
    const int q0 = (r == 0) ? 1 : 0;
    const int q1 = (r == 2) ? 1 : 2;
    const __half* Bsrc = g_Bc + r * 131072;

    float acc[2][4][4];
#pragma unroll
    for (int i = 0; i < 2; i++)
#pragma unroll
        for (int j = 0; j < 4; j++)
#pragma unroll
            for (int v = 0; v < 4; v++) acc[i][j][v] = 0.f;

    {
#pragma unroll
        for (int i = 0; i < 4; i++) {
            int idx = i * 128 + tid;
            int row = idx >> 3, c = idx & 7;
            cp_async16(sb + SMM_A0 + swz(row, c * 8),
                       g_W1h + (size_t)(m0 + row) * KIN + q0 * 256 + c * 8);
            cp_async16(sb + SMM_B0 + swz(row, c * 8),
                       Bsrc + (size_t)(n0 + row) * 512 + c * 8);
        }
        cp_commit();
        cp_wait0();
        __syncthreads();
    }

    const int NITER = 8;
    for (int kc = 0; kc < NITER; kc++) {
        const uint32_t Abase = sb + (kc & 1 ? SMM_A1 : SMM_A0);
        const uint32_t Bbase = sb + (kc & 1 ? SMM_B1 : SMM_B0);
        const int nxt = kc + 1;

        if (nxt < NITER) {
            uint32_t AbaseN = sb + (nxt & 1 ? SMM_A1 : SMM_A0);
            uint32_t BbaseN = sb + (nxt & 1 ? SMM_B1 : SMM_B0);
            int q = (nxt >> 2) ? q1 : q0;
            int colbase = q * 256 + (nxt & 3) * 64;
#pragma unroll
            for (int i = 0; i < 4; i++) {
                int idx = i * 128 + tid;
                int row = idx >> 3, c = idx & 7;
                cp_async16(AbaseN + swz(row, c * 8),
                           g_W1h + (size_t)(m0 + row) * KIN + colbase + c * 8);
                cp_async16(BbaseN + swz(row, c * 8),
                           Bsrc + (size_t)(n0 + row) * 512 + nxt * 64 + c * 8);
            }
            cp_commit();
        }

#pragma unroll
        for (int ks = 0; ks < 64; ks += 16) {
            uint32_t a[2][4], b[8];
#pragma unroll
            for (int t = 0; t < 2; t++) {
                uint32_t row = wm + t * 16 + (lane & 15);
                uint32_t kk  = ks + (lane >> 4) * 8;
                ldm_x4(a[t][0], a[t][1], a[t][2], a[t][3], Abase + swz(row, kk));
            }
#pragma unroll
            for (int h = 0; h < 2; h++) {
                int g = lane >> 3, ri = lane & 7;
                uint32_t nrow = wn + h * 16 + (g >> 1) * 8 + ri;
                uint32_t kk   = ks + (g & 1) * 8;
                ldm_x4(b[h * 4 + 0], b[h * 4 + 1], b[h * 4 + 2], b[h * 4 + 3],
                       Bbase + swz(nrow, kk));
            }
#pragma unroll
            for (int mt = 0; mt < 2; mt++)
#pragma unroll
                for (int nt = 0; nt < 4; nt++)
                    mma16816(acc[mt][nt], a[mt][0], a[mt][1], a[mt][2], a[mt][3],
                             b[nt * 2], b[nt * 2 + 1]);
        }

        if (nxt < NITER) cp_wait0();
        __syncthreads();
    }

#pragma unroll
    for (int mt = 0; mt < 2; mt++) {
#pragma unroll
        for (int nt = 0; nt < 4; nt++) {
            int kp = n0 + wn + nt * 8 + (lane & 3) * 2;
            int nrow0 = m0 + wm + mt * 16 + (lane >> 2);
            size_t base0 = (size_t)nrow0 * KIN + r * 256 + kp;
            size_t base1 = (size_t)(nrow0 + 8) * KIN + r * 256 + kp;
            __half2 h01 = __floats2half2_rn(W1[base0] + acc[mt][nt][0],
                                            W1[base0 + 1] + acc[mt][nt][1]);
            __half2 h23 = __floats2half2_rn(W1[base1] + acc[mt][nt][2],
                                            W1[base1 + 1] + acc[mt][nt][3]);
            *(__half2*)(g_B1h + base0) = h01;
            *(__half2*)(g_B1h + base1) = h23;
        }
    }
}

// ============================================================================
// GEMM1 (R6 winner, at mma.sync ceiling per R14 ncu): UNTOUCHED
// ============================================================================
__global__ void __launch_bounds__(256, 2)
gemm1(const float* __restrict__ gE, const float* __restrict__ dE,
      const float* __restrict__ cE) {
    extern __shared__ char smem[];
    const uint32_t sb = smem_u32(smem);
    const int tid = threadIdx.x;
    const int wid = tid >> 5, lane = tid & 31;
    const int m0 = blockIdx.y * 128;
    const int n0 = blockIdx.x * 128;
    const int wm = (wid >> 2) * 64;
    const int wn = (wid & 3) * 32;
    const float* srcs[3] = {gE, dE, cE};

    float acc[4][4][4];
#pragma unroll
    for (int i = 0; i < 4; i++)
#pragma unroll
        for (int j = 0; j < 4; j++)
#pragma unroll
            for (int v = 0; v < 4; v++) acc[i][j][v] = 0.f;

    const int a_row[8] = { (0*256+tid) >> 4, (1*256+tid) >> 4, (2*256+tid) >> 4, (3*256+tid) >> 4,
                           (4*256+tid) >> 4, (5*256+tid) >> 4, (6*256+tid) >> 4, (7*256+tid) >> 4 };
    const int a_c4 = tid & 15;

    uint2 ah[8];

    {
        const float* src = srcs[0] + (size_t)m0 * 256;
#pragma unroll
        for (int i = 0; i < 8; i++) {
            float4 f = *(const float4*)(src + (size_t)a_row[i] * 256 + a_c4 * 4);
            __half2 h0 = __floats2half2_rn(f.x, f.y);
            __half2 h1 = __floats2half2_rn(f.z, f.w);
            ah[i].x = *(uint32_t*)&h0;
            ah[i].y = *(uint32_t*)&h1;
        }
#pragma unroll
        for (int i = 0; i < 8; i++)
            *(uint2*)(smem + SM_A0 + swz(a_row[i], a_c4 * 4)) = ah[i];
#pragma unroll
        for (int i = 0; i < 4; i++) {
            int idx = i * 256 + tid;
            int row = idx >> 3, c = idx & 7;
            cp_async16(sb + SM_B0 + swz(row, c * 8), g_B1h + (size_t)(n0 + row) * KIN + c * 8);
        }
        cp_commit();
        cp_wait0();
        __syncthreads();
    }

    const int NITER = 12;
    for (int kc = 0; kc < NITER; kc++) {
        const uint32_t Abase = sb + (kc & 1 ? SM_A1 : SM_A0);
        const uint32_t Bbase = sb + (kc & 1 ? SM_B1 : SM_B0);
        const int nxt = kc + 1;
        const uint32_t AbaseN = sb + (nxt & 1 ? SM_A1 : SM_A0);
        const uint32_t BbaseN = sb + (nxt & 1 ? SM_B1 : SM_B0);

        if (nxt < NITER) {
            const float* src = srcs[nxt >> 2] + (size_t)m0 * 256 + (nxt & 3) * 64;
#pragma unroll
            for (int i = 0; i < 8; i++) {
                float4 f = *(const float4*)(src + (size_t)a_row[i] * 256 + a_c4 * 4);
                __half2 h0 = __floats2half2_rn(f.x, f.y);
                __half2 h1 = __floats2half2_rn(f.z, f.w);
                ah[i].x = *(uint32_t*)&h0;
                ah[i].y = *(uint32_t*)&h1;
            }
#pragma unroll
            for (int i = 0; i < 4; i++) {
                int idx = i * 256 + tid;
                int row = idx >> 3, c = idx & 7;
                cp_async16(BbaseN + swz(row, c * 8),
                           g_B1h + (size_t)(n0 + row) * KIN + nxt * 64 + c * 8);
            }
            cp_commit();
        }

#pragma unroll
        for (int ks = 0; ks < 64; ks += 16) {
            uint32_t a[4][4], b[8];
#pragma unroll
            for (int t = 0; t < 4; t++) {
                uint32_t row = wm + t * 16 + (lane & 15);
                uint32_t kk  = ks + (lane >> 4) * 8;
                ldm_x4(a[t][0], a[t][1], a[t][2], a[t][3], Abase + swz(row, kk));
            }
#pragma unroll
            for (int h = 0; h < 2; h++) {
                int g = lane >> 3, ri = lane & 7;
                uint32_t nrow = wn + h * 16 + (g >> 1) * 8 + ri;
                uint32_t kk   = ks + (g & 1) * 8;
                ldm_x4(b[h * 4 + 0], b[h * 4 + 1], b[h * 4 + 2], b[h * 4 + 3],
                       Bbase + swz(nrow, kk));
            }
#pragma unroll
            for (int mt = 0; mt < 4; mt++)
#pragma unroll
                for (int nt = 0; nt < 4; nt++)
                    mma16816(acc[mt][nt], a[mt][0], a[mt][1], a[mt][2], a[mt][3],
                             b[nt * 2], b[nt * 2 + 1]);
        }

        if (nxt < NITER) {
#pragma unroll
            for (int i = 0; i < 8; i++)
                *(uint2*)((char*)smem + (AbaseN - sb) + swz(a_row[i], a_c4 * 4)) = ah[i];
            cp_wait0();
        }
        __syncthreads();
    }

#pragma unroll
    for (int mt = 0; mt < 4; mt++) {
#pragma unroll
        for (int nt = 0; nt < 4; nt++) {
            int n = n0 + wn + nt * 8 + (lane & 3) * 2;
            float bia0 = g_b1eff[n], bia1 = g_b1eff[n + 1];
            int r0 = m0 + wm + mt * 16 + (lane >> 2);
            float v0 = fmaxf(acc[mt][nt][0] + bia0, 0.f);
            float v1 = fmaxf(acc[mt][nt][1] + bia1, 0.f);
            float v2 = fmaxf(acc[mt][nt][2] + bia0, 0.f);
            float v3 = fmaxf(acc[mt][nt][3] + bia1, 0.f);
            __half2 h01 = __floats2half2_rn(v0, v1);
            __half2 h23 = __floats2half2_rn(v2, v3);
            *(__half2*)(g_H + (size_t)r0 * HIDN + n)       = h01;
            *(__half2*)(g_H + (size_t)(r0 + 8) * HIDN + n) = h23;
        }
    }
}

// ============================================================================
// GEMM2: out[B,256] = g_H[B,512] @ W2h^T + b2, fp32 out, occ 2
// 3-STAGE cp.async pipeline (prefetch distance 2); pure-cp.async operands.
// SMEM: A s*16K (s=0..2), B 48K+s*16K = 96KB/CTA; 2 CTAs = 192KB <= 227KB.
// ============================================================================
__global__ void __launch_bounds__(256, 2)
gemm2(const float* __restrict__ b2, float* __restrict__ out) {
    extern __shared__ char smem[];
    const uint32_t sb = smem_u32(smem);
    const int tid = threadIdx.x;
    const int wid = tid >> 5, lane = tid & 31;
    const int m0 = blockIdx.y * 128;
    const int n0 = blockIdx.x * 128;
    const int wm = (wid >> 2) * 64;
    const int wn = (wid & 3) * 32;

    float acc[4][4][4];
#pragma unroll
    for (int i = 0; i < 4; i++)
#pragma unroll
        for (int j = 0; j < 4; j++)
#pragma unroll
            for (int v = 0; v < 4; v++) acc[i][j][v] = 0.f;

    const int NITER = 8;

    // stage-issue helper (inlined twice in prologue, once in loop)
#define G2_ISSUE(kci)  do {                                                          \
        int s_ = (kci) % 3;                                                          \
        uint32_t Ab_ = sb + s_ * 16384;                                              \
        uint32_t Bb_ = sb + 49152 + s_ * 16384;                                      \
        _Pragma("unroll")                                                            \
        for (int i_ = 0; i_ < 4; i_++) {                                             \
            int idx_ = i_ * 256 + tid;                                               \
            int row_ = idx_ >> 3, c_ = idx_ & 7;                                     \
            cp_async16(Ab_ + swz(row_, c_ * 8),                                      \
                       g_H + (size_t)(m0 + row_) * HIDN + (kci) * 64 + c_ * 8);      \
            cp_async16(Bb_ + swz(row_, c_ * 8),                                      \
                       g_W2h + (size_t)(n0 + row_) * HIDN + (kci) * 64 + c_ * 8);    \
        }                                                                            \
        cp_commit();                                                                 \
    } while (0)

    // prologue: prefetch kc=0 and kc=1
    G2_ISSUE(0);
    G2_ISSUE(1);

    for (int kc = 0; kc < NITER; kc++) {
        cp_wait1();          // buffer kc complete; kc+1 may remain in flight
        __syncthreads();     // all warps done with buffer (kc-1)%3 == (kc+2)%3

        if (kc + 2 < NITER) G2_ISSUE(kc + 2);

        const int s = kc % 3;
        const uint32_t Abase = sb + s * 16384;
        const uint32_t Bbase = sb + 49152 + s * 16384;

#pragma unroll
        for (int ks = 0; ks < 64; ks += 16) {
            uint32_t a[4][4], b[8];
#pragma unroll
            for (int t = 0; t < 4; t++) {
                uint32_t row = wm + t * 16 + (lane & 15);
                uint32_t kk  = ks + (lane >> 4) * 8;
                ldm_x4(a[t][0], a[t][1], a[t][2], a[t][3], Abase + swz(row, kk));
            }
#pragma unroll
            for (int h = 0; h < 2; h++) {
                int g = lane >> 3, ri = lane & 7;
                uint32_t nrow = wn + h * 16 + (g >> 1) * 8 + ri;
                uint32_t kk   = ks + (g & 1) * 8;
                ldm_x4(b[h * 4 + 0], b[h * 4 + 1], b[h * 4 + 2], b[h * 4 + 3],
                       Bbase + swz(nrow, kk));
            }
#pragma unroll
            for (int mt = 0; mt < 4; mt++)
#pragma unroll
                for (int nt = 0; nt < 4; nt++)
                    mma16816(acc[mt][nt], a[mt][0], a[mt][1], a[mt][2], a[mt][3],
                             b[nt * 2], b[nt * 2 + 1]);
        }
    }
#undef G2_ISSUE

    // epilogue: acc + b2 -> fp32 out
#pragma unroll
    for (int mt = 0; mt < 4; mt++) {
#pragma unroll
        for (int nt = 0; nt < 4; nt++) {
            int n = n0 + wn + nt * 8 + (lane & 3) * 2;
            float bia0 = b2[n], bia1 = b2[n + 1];
            int r0 = m0 + wm + mt * 16 + (lane >> 2);
            float2 o01 = { acc[mt][nt][0] + bia0, acc[mt][nt][1] + bia1 };
            float2 o23 = { acc[mt][nt][2] + bia0, acc[mt][nt][3] + bia1 };
            *(float2*)(out + (size_t)r0 * EDIM + n)       = o01;
            *(float2*)(out + (size_t)(r0 + 8) * EDIM + n) = o23;
        }
    }
}

// ============================================================================
// kernel_launch
// Input order: g, d, c, Wq, Wk, Wv, bq, bk, bv, Wo, bo, W1, b1, W2, b2
// ============================================================================
extern "C" void kernel_launch(void* const* d_in, const int* in_sizes, int n_in,
                              void* d_out, int out_size) {
    const float* g  = (const float*)d_in[0];
    const float* dd = (const float*)d_in[1];
    const float* cc = (const float*)d_in[2];
    const float* Wv = (const float*)d_in[5];
    const float* bv = (const float*)d_in[8];
    const float* Wo = (const float*)d_in[9];
    const float* bo = (const float*)d_in[10];
    const float* W1 = (const float*)d_in[11];
    const float* b1 = (const float*)d_in[12];
    const float* W2 = (const float*)d_in[13];
    const float* b2 = (const float*)d_in[14];
    const int B = in_sizes[0] / EDIM;

    cudaFuncSetAttribute(k_MmmaB, cudaFuncAttributeMaxDynamicSharedMemorySize, SMEM_M);
    cudaFuncSetAttribute(k_B1mma, cudaFuncAttributeMaxDynamicSharedMemorySize, SMEM_M);
    cudaFuncSetAttribute(gemm1,   cudaFuncAttributeMaxDynamicSharedMemorySize, SMEM_G);
    cudaFuncSetAttribute(gemm2,   cudaFuncAttributeMaxDynamicSharedMemorySize, SMEM_G2);

    // Precompute chain: 3 launches
    k_prep  <<<3974, 256>>>(W1, W2, Wo, Wv, bv, bo);  // fp16 conv + transpose + cvec
    k_MmmaB <<<608, 128, SMEM_M>>>(W1, b1);           // M GEMMs (96) + b1eff (512) merged
    k_B1mma <<<dim3(4, 8, 3), 128, SMEM_M>>>(W1);     // fold (+W1 -> fp16)

    gemm1<<<dim3(4, B / 128), 256, SMEM_G>>>(g, dd, cc);
    gemm2<<<dim3(2, B / 128), 256, SMEM_G2>>>(b2, (float*)d_out);
}